// round 10
// baseline (speedup 1.0000x reference)
#include <cuda_runtime.h>
#include <cuda_bf16.h>
#include <math.h>
#include <stdint.h>

#define SDIM 2048
#define EDIM 2048
#define NH   16
#define NKV  4
#define DH   128
#define NHG  12
#define RDIM 32
#define NSYM 4
#define NOUT 3840
#define CQ   0
#define CK   2048
#define CV   2560
#define CRQ  3072
#define CRK  3456
#define KQ   448

static __device__ float g_pr[SDIM*NOUT];
static __device__ float g_sc[(size_t)NH*SDIM*SDIM];
static __device__ float g_rm[NH*SDIM];
static __device__ float g_ri[NH*SDIM];
static __device__ __nv_bfloat16 g_xh [SDIM*EDIM];
static __device__ __nv_bfloat16 g_xl [SDIM*EDIM];
static __device__ __nv_bfloat16 g_wh [(size_t)NOUT*EDIM];
static __device__ __nv_bfloat16 g_wl [(size_t)NOUT*EDIM];
static __device__ __nv_bfloat16 g_woh[(size_t)EDIM*EDIM];
static __device__ __nv_bfloat16 g_wol[(size_t)EDIM*EDIM];
static __device__ __nv_bfloat16 g_aoh[(size_t)SDIM*EDIM];
static __device__ __nv_bfloat16 g_aol[(size_t)SDIM*EDIM];
static __device__ __nv_bfloat16 g_qa [(size_t)NH*SDIM*KQ];
static __device__ __nv_bfloat16 g_kb [(size_t)NH*SDIM*KQ];
static __device__ __nv_bfloat16 g_vth[(size_t)NKV*DH*SDIM];
static __device__ __nv_bfloat16 g_vtl[(size_t)NKV*DH*SDIM];

// ---------------- PTX helpers ----------------
__device__ __forceinline__ uint32_t smem_u32(const void* p) {
    uint32_t a;
    asm("{ .reg .u64 t; cvta.to.shared.u64 t, %1; cvt.u32.u64 %0, t; }" : "=r"(a) : "l"(p));
    return a;
}
__device__ __forceinline__ void cpa16(uint32_t d, const void* g) {
    asm volatile("cp.async.cg.shared.global [%0], [%1], 16;" :: "r"(d), "l"(g));
}
__device__ __forceinline__ void cp_commit() { asm volatile("cp.async.commit_group;" ::: "memory"); }
template<int N> __device__ __forceinline__ void cp_wait() {
    asm volatile("cp.async.wait_group %0;" :: "n"(N) : "memory");
}
__device__ __forceinline__ void ldm_x4(uint32_t& r0, uint32_t& r1, uint32_t& r2, uint32_t& r3,
                                       uint32_t addr) {
    asm volatile("ldmatrix.sync.aligned.m8n8.x4.shared.b16 {%0,%1,%2,%3}, [%4];"
                 : "=r"(r0), "=r"(r1), "=r"(r2), "=r"(r3) : "r"(addr));
}
__device__ __forceinline__ void mma_bf16(float* d, const uint32_t* a, const uint32_t* b) {
    asm volatile("mma.sync.aligned.m16n8k16.row.col.f32.bf16.bf16.f32 "
                 "{%0,%1,%2,%3}, {%4,%5,%6,%7}, {%8,%9}, {%0,%1,%2,%3};"
                 : "+f"(d[0]), "+f"(d[1]), "+f"(d[2]), "+f"(d[3])
                 : "r"(a[0]), "r"(a[1]), "r"(a[2]), "r"(a[3]), "r"(b[0]), "r"(b[1]));
}
__device__ __forceinline__ void fold2(float v, uint32_t& H, uint32_t& L) {
    __nv_bfloat16 h = __float2bfloat16(v);
    __nv_bfloat16 l = __float2bfloat16(v - __bfloat162float(h));
    H = __bfloat16_as_ushort(h); L = __bfloat16_as_ushort(l);
}
__device__ __forceinline__ void sbody(const float* s, __nv_bfloat16* dh, __nv_bfloat16* dl, int i) {
    float2 v = ((const float2*)s)[i];
    uint32_t H0, L0, H1, L1;
    fold2(v.x, H0, L0); fold2(v.y, H1, L1);
    ((uint32_t*)dh)[i] = H0 | (H1 << 16);
    ((uint32_t*)dl)[i] = L0 | (L1 << 16);
}

__global__ __launch_bounds__(256) void split_sep(
    const float* __restrict__ s, __nv_bfloat16* __restrict__ dh,
    __nv_bfloat16* __restrict__ dl, int npairs)
{
    int i = blockIdx.x * 256 + threadIdx.x;
    if (i < npairs) sbody(s, dh, dl, i);
}
__global__ __launch_bounds__(256) void split_rest(
    const float* __restrict__ wk, const float* __restrict__ wv,
    const float* __restrict__ wrq, const float* __restrict__ wrk,
    const float* __restrict__ wo)
{
    int i = blockIdx.x * 256 + threadIdx.x;
    const int A = 524288, B = 1048576, C = 1441792, D = 1835008, E = 3932160;
    if      (i < A) sbody(wk,  g_wh + (size_t)CK  * EDIM, g_wl + (size_t)CK  * EDIM, i);
    else if (i < B) sbody(wv,  g_wh + (size_t)CV  * EDIM, g_wl + (size_t)CV  * EDIM, i - A);
    else if (i < C) sbody(wrq, g_wh + (size_t)CRQ * EDIM, g_wl + (size_t)CRQ * EDIM, i - B);
    else if (i < D) sbody(wrk, g_wh + (size_t)CRK * EDIM, g_wl + (size_t)CRK * EDIM, i - C);
    else if (i < E) sbody(wo,  g_woh, g_wol, i - D);
}

// ---------------- shared machinery ----------------
#define GEMM_PREAMBLE                                                           \
    extern __shared__ __align__(1024) char dsm[];                               \
    const uint32_t sb = smem_u32(dsm);                                          \
    const int tid = threadIdx.x;                                                \
    const int l = tid & 31, wid = tid >> 5;                                     \
    const int cch = tid & 7;                                                    \
    const int akh = (l >> 4);                                                   \
    const int bkh = (l >> 3) & 1;                                               \
    const int lsw = l & 7;

#define LOAD128(base, P, ld, step) do {                                         \
    const __nv_bfloat16* G = (P) + (size_t)(step) * 64;                         \
    _Pragma("unroll")                                                           \
    for (int it = 0; it < 4; it++) {                                            \
        int row = (tid >> 3) + 32 * it;                                         \
        uint32_t sw = row * 128u + 16u * (cch ^ (row & 7));                     \
        cpa16((base) + sw, G + (size_t)row * (ld) + cch * 8);                   \
    } } while (0)

// separated hi/lo stage rows: 128B row = [H(32 bf16) | L(32 bf16)], 32 raw K/stage
#define LOADSEP_B(base, Ph, Pl, ld, step) do {                                   \
    _Pragma("unroll")                                                           \
    for (int it = 0; it < 4; it++) {                                            \
        int row = (tid >> 3) + 32 * it;                                         \
        const __nv_bfloat16* src = ((cch < 4) ? (Ph) : (Pl))                    \
            + (size_t)row * (ld) + (size_t)(step) * 32 + (cch & 3) * 8;         \
        cpa16((base) + row * 128u + 16u * ((uint32_t)cch ^ (row & 7)), src);    \
    } } while (0)

#define LOADSEP_A(base, Ph, Pl, ld, step) do {                                   \
    _Pragma("unroll")                                                           \
    for (int it = 0; it < 2; it++) {                                            \
        int row = (tid >> 3) + 32 * it;                                         \
        const __nv_bfloat16* src = ((cch < 4) ? (Ph) : (Pl))                    \
            + (size_t)row * (ld) + (size_t)(step) * 32 + (cch & 3) * 8;         \
        cpa16((base) + row * 128u + 16u * ((uint32_t)cch ^ (row & 7)), src);    \
    } } while (0)

#define INNER_128(Ab, Bb)                                                       \
    _Pragma("unroll")                                                           \
    for (int kk = 0; kk < 4; kk++) {                                            \
        uint32_t af[4][4], bf[4][2];                                            \
        _Pragma("unroll")                                                       \
        for (int tm = 0; tm < 4; tm++)                                          \
            ldm_x4(af[tm][0], af[tm][1], af[tm][2], af[tm][3],                  \
                   (Ab) + (uint32_t)(ar + tm * 16) * 128u + 16u * (((kk << 1) + akh) ^ lsw)); \
        _Pragma("unroll")                                                       \
        for (int np = 0; np < 2; np++) {                                        \
            uint32_t r0, r1, r2, r3;                                            \
            ldm_x4(r0, r1, r2, r3,                                              \
                   (Bb) + (uint32_t)(br + np * 16) * 128u + 16u * (((kk << 1) + bkh) ^ lsw)); \
            bf[2*np][0] = r0; bf[2*np][1] = r1; bf[2*np+1][0] = r2; bf[2*np+1][1] = r3; \
        }                                                                       \
        _Pragma("unroll")                                                       \
        for (int tm = 0; tm < 4; tm++)                                          \
            _Pragma("unroll")                                                   \
            for (int tn = 0; tn < 4; tn++) mma_bf16(acc[tm][tn], af[tm], bf[tn]); \
    }

// ---------------- 3-product separated-fold GEMM: CTA 64x128, occ 3 ----------
// smem/stage: A 8KB @ +0, B 16KB @ +8192; 2 stages, stride 24576 (48KB total)
__global__ __launch_bounds__(256, 3) void gemm3(
    const __nv_bfloat16* __restrict__ Ah, const __nv_bfloat16* __restrict__ Al,
    const __nv_bfloat16* __restrict__ Bh, const __nv_bfloat16* __restrict__ Bl,
    float* __restrict__ C, int ldc, int K)
{
    GEMM_PREAMBLE
    const int wm = wid & 1, wn = wid >> 1;
    const int m0 = blockIdx.y << 6, n0 = blockIdx.x << 7;
    const int steps = K >> 5;
    const __nv_bfloat16* Ah_ = Ah + (size_t)m0 * K;
    const __nv_bfloat16* Al_ = Al + (size_t)m0 * K;
    const __nv_bfloat16* Bh_ = Bh + (size_t)n0 * K;
    const __nv_bfloat16* Bl_ = Bl + (size_t)n0 * K;

    float acc[2][4][4];
#pragma unroll
    for (int i = 0; i < 2; i++)
#pragma unroll
        for (int j = 0; j < 4; j++)
#pragma unroll
            for (int r = 0; r < 4; r++) acc[i][j][r] = 0.f;

    const int ar = wm * 32 + (l & 7) + (l & 8);
    const int br = wn * 32 + (l & 7) + 8 * (l >> 4);

    LOADSEP_A(sb, Ah_, Al_, K, 0);
    LOADSEP_B(sb + 8192u, Bh_, Bl_, K, 0);
    cp_commit();

    for (int s = 0; s < steps; s++) {
        cp_wait<0>();
        __syncthreads();
        if (s + 1 < steps) {
            uint32_t b2 = sb + ((s + 1) & 1) * 24576u;
            LOADSEP_A(b2, Ah_, Al_, K, s + 1);
            LOADSEP_B(b2 + 8192u, Bh_, Bl_, K, s + 1);
            cp_commit();
        }
        const uint32_t Ab = sb + (s & 1) * 24576u;
        const uint32_t Bb = Ab + 8192u;
#pragma unroll
        for (int ch = 0; ch < 3; ch++) {
            const int ao = (ch == 2) ? 4 : 0;
            const int bo = (ch == 1) ? 4 : 0;
#pragma unroll
            for (int kk = 0; kk < 2; kk++) {
                uint32_t af[2][4], bf[4][2];
#pragma unroll
                for (int tm = 0; tm < 2; tm++)
                    ldm_x4(af[tm][0], af[tm][1], af[tm][2], af[tm][3],
                           Ab + (uint32_t)(ar + tm * 16) * 128u
                              + 16u * ((((kk << 1) + akh + ao)) ^ lsw));
#pragma unroll
                for (int np = 0; np < 2; np++) {
                    uint32_t r0, r1, r2, r3;
                    ldm_x4(r0, r1, r2, r3,
                           Bb + (uint32_t)(br + np * 16) * 128u
                              + 16u * ((((kk << 1) + bkh + bo)) ^ lsw));
                    bf[2*np][0] = r0; bf[2*np][1] = r1; bf[2*np+1][0] = r2; bf[2*np+1][1] = r3;
                }
#pragma unroll
                for (int tm = 0; tm < 2; tm++)
#pragma unroll
                    for (int tn = 0; tn < 4; tn++) mma_bf16(acc[tm][tn], af[tm], bf[tn]);
            }
        }
    }
    const int er = m0 + wm * 32 + (l >> 2);
    const int ec = n0 + wn * 32 + 2 * (l & 3);
#pragma unroll
    for (int tm = 0; tm < 2; tm++)
#pragma unroll
        for (int tn = 0; tn < 4; tn++) {
            float* p0 = C + (size_t)(er + tm * 16) * ldc + ec + tn * 8;
            float* p1 = C + (size_t)(er + tm * 16 + 8) * ldc + ec + tn * 8;
            *(float2*)p0 = make_float2(acc[tm][tn][0], acc[tm][tn][1]);
            *(float2*)p1 = make_float2(acc[tm][tn][2], acc[tm][tn][3]);
        }
}

// ---------------- scores on tensor cores (unchanged) ----------------
__global__ __launch_bounds__(256) void scores_mma()
{
    GEMM_PREAMBLE
    const int wm = wid & 1, wn = wid >> 1;
    const int h = blockIdx.y, idx = blockIdx.x;
    int ti = (int)((sqrtf(8.f * idx + 1.f) - 1.f) * 0.5f);
    while ((ti + 1) * (ti + 2) / 2 <= idx) ti++;
    while (ti * (ti + 1) / 2 > idx) ti--;
    const int tj = idx - ti * (ti + 1) / 2;
    const int i0 = ti << 7, j0 = tj << 7;
    const __nv_bfloat16* Ab_ = g_qa + ((size_t)h * SDIM + i0) * KQ;
    const __nv_bfloat16* Bb_ = g_kb + ((size_t)h * SDIM + j0) * KQ;
    const int steps = KQ >> 6;

    float acc[4][4][4];
#pragma unroll
    for (int i = 0; i < 4; i++)
#pragma unroll
        for (int j = 0; j < 4; j++)
#pragma unroll
            for (int r = 0; r < 4; r++) acc[i][j][r] = 0.f;
    const int ar = wm * 64 + (l & 7) + (l & 8);
    const int br = wn * 32 + (l & 7) + 8 * (l >> 4);

    LOAD128(sb, Ab_, KQ, 0); LOAD128(sb + 16384u, Bb_, KQ, 0); cp_commit();
    LOAD128(sb + 32768u, Ab_, KQ, 1); LOAD128(sb + 49152u, Bb_, KQ, 1); cp_commit();

    for (int s = 0; s < steps; s++) {
        cp_wait<1>();
        __syncthreads();
        if (s + 2 < steps) {
            uint32_t b2 = sb + ((s + 2) % 3) * 32768u;
            LOAD128(b2, Ab_, KQ, s + 2); LOAD128(b2 + 16384u, Bb_, KQ, s + 2);
        }
        cp_commit();
        const uint32_t Ab = sb + (s % 3) * 32768u;
        const uint32_t Bb = Ab + 16384u;
        INNER_128(Ab, Bb)
    }
    const int er = i0 + wm * 64 + (l >> 2);
    const int ec = j0 + wn * 32 + 2 * (l & 3);
#pragma unroll
    for (int tm = 0; tm < 4; tm++)
#pragma unroll
        for (int tn = 0; tn < 4; tn++) {
            int r0 = er + tm * 16, r1 = r0 + 8, c = ec + tn * 8;
            float* p0 = g_sc + ((size_t)h * SDIM + r0) * SDIM + c;
            float* p1 = g_sc + ((size_t)h * SDIM + r1) * SDIM + c;
            *(float2*)p0 = make_float2(c     <= r0 ? acc[tm][tn][0] : 0.f,
                                       c + 1 <= r0 ? acc[tm][tn][1] : 0.f);
            *(float2*)p1 = make_float2(c     <= r1 ? acc[tm][tn][2] : 0.f,
                                       c + 1 <= r1 ? acc[tm][tn][3] : 0.f);
        }
}

// ---------------- rowstat ----------------
__global__ __launch_bounds__(256) void rowstat()
{
    const int i = blockIdx.x, h = blockIdx.y;
    const int len = i + 1;
    const float* row = g_sc + ((size_t)h * SDIM + i) * SDIM;
    __shared__ float buf[SDIM];
    __shared__ float red[8];
    const int tid = threadIdx.x;

    float m = -3.4e38f;
    for (int j = tid; j < len; j += 256) { float v = row[j]; buf[j] = v; m = fmaxf(m, v); }
#pragma unroll
    for (int o = 16; o; o >>= 1) m = fmaxf(m, __shfl_xor_sync(0xffffffffu, m, o));
    if ((tid & 31) == 0) red[tid >> 5] = m;
    __syncthreads();
    m = red[0];
#pragma unroll
    for (int q = 1; q < 8; q++) m = fmaxf(m, red[q]);
    __syncthreads();

    float sum = 0.f;
    for (int j = tid; j < len; j += 256) sum += __expf(buf[j] - m);
#pragma unroll
    for (int o = 16; o; o >>= 1) sum += __shfl_xor_sync(0xffffffffu, sum, o);
    if ((tid & 31) == 0) red[tid >> 5] = sum;
    __syncthreads();
    if (tid == 0) {
        sum = red[0] + red[1] + red[2] + red[3] + red[4] + red[5] + red[6] + red[7];
        g_rm[h * SDIM + i] = m;
        g_ri[h * SDIM + i] = 1.f / sum;
    }
}

// ---------------- AV fused (unchanged) ----------------
__global__ __launch_bounds__(256) void av_mma()
{
    extern __shared__ __align__(1024) char dsm[];
    const uint32_t sb = smem_u32(dsm);
    const int tid = threadIdx.x;
    const int l = tid & 31, wid = tid >> 5;
    const int cch = tid & 7;
    const int akh = (l >> 4);
    const int bkh = (l >> 3) & 1;
    const int lsw = l & 7;
    const int wm = wid & 1, wn = wid >> 1;
    const int h = blockIdx.y;
    const __nv_bfloat16* Vh_ = g_vth + (size_t)(h >> 2) * DH * SDIM;
    const __nv_bfloat16* Vl_ = g_vtl + (size_t)(h >> 2) * DH * SDIM;

    const int ar = wm * 32 + (l & 7) + (l & 8);
    const int br = wn * 32 + (l & 7) + 8 * (l >> 4);
    const int pr_ = tid >> 2;
    const int pc0 = (tid & 3) << 4;

    for (int half = 0; half < 2; half++) {
        const int mt = half ? 31 - (int)blockIdx.x : (int)blockIdx.x;
        const int m0 = mt << 6;
        const int njt = mt + 1;

        float acc[2][4][4];
#pragma unroll
        for (int i = 0; i < 2; i++)
#pragma unroll
            for (int j = 0; j < 4; j++)
#pragma unroll
                for (int r = 0; r < 4; r++) acc[i][j][r] = 0.f;

        LOAD128(sb + 32768u, Vh_, SDIM, 0);
        LOAD128(sb + 49152u, Vl_, SDIM, 0);
        cp_commit();

        const int grow = m0 + pr_;
        const float mrow = g_rm[h * SDIM + grow];
        const float irow = g_ri[h * SDIM + grow];
        const float* srow0 = g_sc + ((size_t)h * SDIM + grow) * SDIM + pc0;

        for (int jt = 0; jt < njt; jt++) {
            const int buf = jt & 1;
            const uint32_t AHo = buf * 16384u;
            const uint32_t ALo = AHo + 8192u;
            const uint32_t BH = sb + 32768u + buf * 32768u;
            const uint32_t BL = BH + 16384u;
            {
                const float* srow = srow0 + jt * 64;
                float4 s0 = *(const float4*)(srow);
                float4 s1 = *(const float4*)(srow + 4);
                float4 s2 = *(const float4*)(srow + 8);
                float4 s3 = *(const float4*)(srow + 12);
                float sv[16] = {s0.x,s0.y,s0.z,s0.w, s1.x,s1.y,s1.z,s1.w,
                                s2.x,s2.y,s2.z,s2.w, s3.x,s3.y,s3.z,s3.w};
#pragma unroll
                for (int p = 0; p < 8; p++) {
                    int c = pc0 + 2 * p;
                    int gc = jt * 64 + c;
                    float p0 = (gc     <= grow) ? __expf(sv[2*p]   - mrow) * irow : 0.f;
                    float p1 = (gc + 1 <= grow) ? __expf(sv[2*p+1] - mrow) * irow : 0.f;
                    uint32_t H0, L0, H1, L1;
                    fold2(p0, H0, L0); fold2(p1, H1, L1);
                    uint32_t byte = (uint32_t)pr_ * 128u
                                  + ((((c >> 3) ^ (pr_ & 7)) & 7) << 4) + ((c & 7) << 1);
                    *(uint32_t*)(dsm + AHo + byte) = H0 | (H1 << 16);
                    *(uint32_t*)(dsm + ALo + byte) = L0 | (L1 << 16);
                }
            }
            cp_wait<0>();
            __syncthreads();
            if (jt + 1 < njt) {
                uint32_t B2 = sb + 32768u + (buf ^ 1) * 32768u;
                LOAD128(B2, Vh_, SDIM, jt + 1);
                LOAD128(B2 + 16384u, Vl_, SDIM, jt + 1);
                cp_commit();
            }
            const uint32_t Ac[3] = {sb + AHo, sb + AHo, sb + ALo};
            const uint32_t Bc[3] = {BH, BL, BH};
#pragma unroll
            for (int ch = 0; ch < 3; ch++) {
                const uint32_t Ab = Ac[ch], Bb = Bc[ch];
#pragma unroll
                for (int kk = 0; kk < 4; kk++) {
                    uint32_t af[2][4], bf[4][2];
#pragma unroll
                    for (int tm = 0; tm < 2; tm++)
                        ldm_x4(af[tm][0], af[tm][1], af[tm][2], af[tm][3],
                               Ab + (uint32_t)(ar + tm * 16) * 128u + 16u * (((kk << 1) + akh) ^ lsw));
#pragma unroll
                    for (int np = 0; np < 2; np++) {
                        uint32_t r0, r1, r2, r3;
                        ldm_x4(r0, r1, r2, r3,
                               Bb + (uint32_t)(br + np * 16) * 128u + 16u * (((kk << 1) + bkh) ^ lsw));
                        bf[2*np][0] = r0; bf[2*np][1] = r1; bf[2*np+1][0] = r2; bf[2*np+1][1] = r3;
                    }
#pragma unroll
                    for (int tm = 0; tm < 2; tm++)
#pragma unroll
                        for (int tn = 0; tn < 4; tn++) mma_bf16(acc[tm][tn], af[tm], bf[tn]);
                }
            }
        }
        const int er = m0 + wm * 32 + (l >> 2);
        const int ecl = wn * 32 + 2 * (l & 3);
#pragma unroll
        for (int tm = 0; tm < 2; tm++)
#pragma unroll
            for (int tn = 0; tn < 4; tn++) {
                int c = h * DH + ecl + tn * 8;
                int r0 = er + tm * 16, r1 = r0 + 8;
#pragma unroll
                for (int rr = 0; rr < 2; rr++) {
                    int row = rr ? r1 : r0;
                    float v0 = acc[tm][tn][rr ? 2 : 0];
                    float v1 = acc[tm][tn][rr ? 3 : 1];
                    uint32_t H0, L0, H1, L1;
                    fold2(v0, H0, L0); fold2(v1, H1, L1);
                    ((uint32_t*)g_aoh)[(size_t)row * (EDIM/2) + (c >> 1)] = H0 | (H1 << 16);
                    ((uint32_t*)g_aol)[(size_t)row * (EDIM/2) + (c >> 1)] = L0 | (L1 << 16);
                }
            }
        __syncthreads();
    }
}

// ---------------- fused RMSNorm + RoPE + fold into qa ----------------
__global__ __launch_bounds__(128) void norm_fill_qa(
    const float* __restrict__ w, const float* __restrict__ gscale)
{
    const int s = blockIdx.x, h = blockIdx.y, d = threadIdx.x;
    float v = g_pr[(size_t)s * NOUT + CQ + h * DH + d];
    float ss = v * v;
#pragma unroll
    for (int o = 16; o; o >>= 1) ss += __shfl_xor_sync(0xffffffffu, ss, o);
    __shared__ float r4[4];
    __shared__ float sh[DH];
    if ((d & 31) == 0) r4[d >> 5] = ss;
    __syncthreads();
    float nv = v * rsqrtf((r4[0]+r4[1]+r4[2]+r4[3]) * (1.f / DH) + 1e-6f) * w[d];
    sh[d] = nv;
    __syncthreads();
    const int dm = d & 63;
    float f = 1.f / powf(10000.f, (float)(2 * dm) * (1.f / DH));
    float cs, sn; sincosf((float)s * f, &sn, &cs);
    float rot = (d < 64) ? -sh[d + 64] : sh[d - 64];
    float qs = (nv * cs + rot * sn) * 0.08838834764831845f;

    __nv_bfloat16* row = g_qa + ((size_t)h * SDIM + s) * KQ;
    uint32_t H, L; fold2(qs, H, L);
    row[3*d]   = __ushort_as_bfloat16((unsigned short)H);
    row[3*d+1] = __ushort_as_bfloat16((unsigned short)H);
    row[3*d+2] = __ushort_as_bfloat16((unsigned short)L);
    if (d < 32) {
        float bv = 0.f;
        if (h < NHG) bv = gscale[h] * (h < NSYM ? 0.5f : 1.f)
                         * g_pr[(size_t)s * NOUT + CRQ + h * RDIM + d];
        row[384 + d] = __float2bfloat16(bv);
    } else if (d < 64) {
        int r = d - 32;
        float bv = 0.f;
        if (h < NSYM) bv = gscale[h] * 0.5f * g_pr[(size_t)s * NOUT + CRK + h * RDIM + r];
        row[416 + r] = __float2bfloat16(bv);
    }
}

// ---------------- fused RMSNorm + RoPE + fold into kb ----------------
__global__ __launch_bounds__(128) void norm_fill_kb(const float* __restrict__ w)
{
    const int s = blockIdx.x, kvh = blockIdx.y, d = threadIdx.x;
    float v = g_pr[(size_t)s * NOUT + CK + kvh * DH + d];
    float ss = v * v;
#pragma unroll
    for (int o = 16; o; o >>= 1) ss += __shfl_xor_sync(0xffffffffu, ss, o);
    __shared__ float r4[4];
    __shared__ float sh[DH];
    if ((d & 31) == 0) r4[d >> 5] = ss;
    __syncthreads();
    float nv = v * rsqrtf((r4[0]+r4[1]+r4[2]+r4[3]) * (1.f / DH) + 1e-6f) * w[d];
    sh[d] = nv;
    __syncthreads();
    const int dm = d & 63;
    float f = 1.f / powf(10000.f, (float)(2 * dm) * (1.f / DH));
    float cs, sn; sincosf((float)s * f, &sn, &cs);
    float rot = (d < 64) ? -sh[d + 64] : sh[d - 64];
    float kf = nv * cs + rot * sn;
    uint32_t H, L; fold2(kf, H, L);

#pragma unroll
    for (int e = 0; e < 4; e++) {
        int h = kvh * 4 + e;
        __nv_bfloat16* row = g_kb + ((size_t)h * SDIM + s) * KQ;
        row[3*d]   = __ushort_as_bfloat16((unsigned short)H);
        row[3*d+1] = __ushort_as_bfloat16((unsigned short)L);
        row[3*d+2] = __ushort_as_bfloat16((unsigned short)H);
        if (d < 32) {
            float bv = (h < NHG) ? g_pr[(size_t)s * NOUT + CRK + h * RDIM + d] : 0.f;
            row[384 + d] = __float2bfloat16(bv);
        } else if (d < 64) {
            int r = d - 32;
            float bv = (h < NSYM) ? g_pr[(size_t)s * NOUT + CRQ + h * RDIM + r] : 0.f;
            row[416 + r] = __float2bfloat16(bv);
        }
    }
}

// ---------------- fill vth/vtl (smem transpose) ----------------
__global__ __launch_bounds__(128) void fill_vhl()
{
    __shared__ float sm[64][129];
    const int jb = blockIdx.x, kvh = blockIdx.y;
    const int tid = threadIdx.x;
    for (int jj = 0; jj < 64; jj++)
        sm[jj][tid] = g_pr[(size_t)(jb * 64 + jj) * NOUT + CV + kvh * DH + tid];
    __syncthreads();
    const int w = tid >> 5, ln = tid & 31;
    for (int d = w; d < DH; d += 4) {
        float v0 = sm[2*ln][d], v1 = sm[2*ln+1][d];
        uint32_t H0, L0, H1, L1;
        fold2(v0, H0, L0); fold2(v1, H1, L1);
        uint32_t* oh = (uint32_t*)(g_vth + (size_t)(kvh * DH + d) * SDIM + jb * 64);
        uint32_t* ol = (uint32_t*)(g_vtl + (size_t)(kvh * DH + d) * SDIM + jb * 64);
        oh[ln] = H0 | (H1 << 16);
        ol[ln] = L0 | (L1 << 16);
    }
}

// ---------------- Host ----------------
extern "C" void kernel_launch(void* const* d_in, const int* in_sizes, int n_in,
                              void* d_out, int out_size)
{
    const float* x   = (const float*)d_in[0];
    const float* Wq  = (const float*)d_in[1];
    const float* Wk  = (const float*)d_in[2];
    const float* Wv  = (const float*)d_in[3];
    const float* Wo  = (const float*)d_in[4];
    const float* qnw = (const float*)d_in[5];
    const float* knw = (const float*)d_in[6];
    const float* Wrq = (const float*)d_in[7];
    const float* Wrk = (const float*)d_in[8];
    const float* gsc = (const float*)d_in[9];
    float* out = (float*)d_out;

    float* pr;
    __nv_bfloat16 *xh, *xl, *wh, *wl, *woh, *wol, *aoh, *aol;
    cudaGetSymbolAddress((void**)&pr,  g_pr);
    cudaGetSymbolAddress((void**)&xh,  g_xh);
    cudaGetSymbolAddress((void**)&xl,  g_xl);
    cudaGetSymbolAddress((void**)&wh,  g_wh);
    cudaGetSymbolAddress((void**)&wl,  g_wl);
    cudaGetSymbolAddress((void**)&woh, g_woh);
    cudaGetSymbolAddress((void**)&wol, g_wol);
    cudaGetSymbolAddress((void**)&aoh, g_aoh);
    cudaGetSymbolAddress((void**)&aol, g_aol);

    cudaFuncSetAttribute(gemm3,      cudaFuncAttributeMaxDynamicSharedMemorySize, 49152);
    cudaFuncSetAttribute(scores_mma, cudaFuncAttributeMaxDynamicSharedMemorySize, 98304);
    cudaFuncSetAttribute(av_mma,     cudaFuncAttributeMaxDynamicSharedMemorySize, 98304);

    split_sep<<<8192, 256>>>(x,  xh, xl, SDIM*EDIM/2);
    split_sep<<<8192, 256>>>(Wq, wh, wl, EDIM*EDIM/2);
    split_rest<<<15360, 256>>>(Wk, Wv, Wrq, Wrk, Wo);

    // index 3 under ncu: merged projection GEMM (CTA 64x128, occ 3)
    gemm3<<<dim3(NOUT/128, SDIM/64), 256, 49152>>>(xh, xl, wh, wl, pr, NOUT, EDIM);

    norm_fill_qa<<<dim3(SDIM, NH),  128>>>(qnw, gsc);
    norm_fill_kb<<<dim3(SDIM, NKV), 128>>>(knw);
    fill_vhl<<<dim3(SDIM/64, NKV), 128>>>();

    scores_mma<<<dim3(136, NH), 256, 98304>>>();
    rowstat<<<dim3(SDIM, NH), 256>>>();
    av_mma<<<dim3(16, NH), 256, 98304>>>();

    gemm3<<<dim3(EDIM/128, SDIM/64), 256, 49152>>>(aoh, aol, woh, wol, out, EDIM, EDIM);
}

// round 11
// speedup vs baseline: 1.4578x; 1.4578x over previous
#include <cuda_runtime.h>
#include <cuda_fp16.h>
#include <math.h>
#include <stdint.h>

#define SDIM 2048
#define EDIM 2048
#define NH   16
#define NKV  4
#define DH   128
#define NHG  12
#define RDIM 32
#define NSYM 4
#define NOUT 3840
#define CQ   0
#define CK   2048
#define CV   2560
#define CRQ  3072
#define CRK  3456
#define KQ   320

static __device__ float g_pr[SDIM*NOUT];
static __device__ float g_sc[(size_t)NH*SDIM*SDIM];
static __device__ float g_rm[NH*SDIM];
static __device__ float g_ri[NH*SDIM];
static __device__ __half g_xh [SDIM*EDIM];
static __device__ __half g_xl [SDIM*EDIM];
static __device__ __half g_wh [(size_t)NOUT*EDIM];
static __device__ __half g_woh[(size_t)EDIM*EDIM];
static __device__ __half g_aoh[(size_t)SDIM*EDIM];
static __device__ __half g_aol[(size_t)SDIM*EDIM];
static __device__ __half g_qa [(size_t)NH*SDIM*KQ];
static __device__ __half g_kb [(size_t)NH*SDIM*KQ];
static __device__ __half g_vth[(size_t)NKV*DH*SDIM];

// ---------------- PTX helpers ----------------
__device__ __forceinline__ uint32_t smem_u32(const void* p) {
    uint32_t a;
    asm("{ .reg .u64 t; cvta.to.shared.u64 t, %1; cvt.u32.u64 %0, t; }" : "=r"(a) : "l"(p));
    return a;
}
__device__ __forceinline__ void cpa16(uint32_t d, const void* g) {
    asm volatile("cp.async.cg.shared.global [%0], [%1], 16;" :: "r"(d), "l"(g));
}
__device__ __forceinline__ void cp_commit() { asm volatile("cp.async.commit_group;" ::: "memory"); }
template<int N> __device__ __forceinline__ void cp_wait() {
    asm volatile("cp.async.wait_group %0;" :: "n"(N) : "memory");
}
__device__ __forceinline__ void ldm_x4(uint32_t& r0, uint32_t& r1, uint32_t& r2, uint32_t& r3,
                                       uint32_t addr) {
    asm volatile("ldmatrix.sync.aligned.m8n8.x4.shared.b16 {%0,%1,%2,%3}, [%4];"
                 : "=r"(r0), "=r"(r1), "=r"(r2), "=r"(r3) : "r"(addr));
}
__device__ __forceinline__ void mma_f16(float* d, const uint32_t* a, const uint32_t* b) {
    asm volatile("mma.sync.aligned.m16n8k16.row.col.f32.f16.f16.f32 "
                 "{%0,%1,%2,%3}, {%4,%5,%6,%7}, {%8,%9}, {%0,%1,%2,%3};"
                 : "+f"(d[0]), "+f"(d[1]), "+f"(d[2]), "+f"(d[3])
                 : "r"(a[0]), "r"(a[1]), "r"(a[2]), "r"(a[3]), "r"(b[0]), "r"(b[1]));
}
__device__ __forceinline__ void fold2h(float v, uint32_t& H, uint32_t& L) {
    __half h = __float2half_rn(v);
    __half l = __float2half_rn(v - __half2float(h));
    H = __half_as_ushort(h); L = __half_as_ushort(l);
}
__device__ __forceinline__ void sbody2(const float* s, __half* dh, __half* dl, int i) {
    float2 v = ((const float2*)s)[i];
    uint32_t H0, L0, H1, L1;
    fold2h(v.x, H0, L0); fold2h(v.y, H1, L1);
    ((uint32_t*)dh)[i] = H0 | (H1 << 16);
    ((uint32_t*)dl)[i] = L0 | (L1 << 16);
}
__device__ __forceinline__ void sbody1(const float* s, __half* dh, int i) {
    float2 v = ((const float2*)s)[i];
    __half h0 = __float2half_rn(v.x), h1 = __float2half_rn(v.y);
    ((uint32_t*)dh)[i] = (uint32_t)__half_as_ushort(h0)
                       | ((uint32_t)__half_as_ushort(h1) << 16);
}

__global__ __launch_bounds__(256) void split_x(
    const float* __restrict__ s, __half* __restrict__ dh,
    __half* __restrict__ dl, int npairs)
{
    int i = blockIdx.x * 256 + threadIdx.x;
    if (i < npairs) sbody2(s, dh, dl, i);
}
__global__ __launch_bounds__(256) void split_w1(
    const float* __restrict__ wq, const float* __restrict__ wk,
    const float* __restrict__ wv)
{
    int i = blockIdx.x * 256 + threadIdx.x;
    const int A = 2097152, B = 2621440, C = 3145728;
    if      (i < A) sbody1(wq, g_wh + (size_t)CQ * EDIM, i);
    else if (i < B) sbody1(wk, g_wh + (size_t)CK * EDIM, i - A);
    else if (i < C) sbody1(wv, g_wh + (size_t)CV * EDIM, i - B);
}
__global__ __launch_bounds__(256) void split_w2(
    const float* __restrict__ wrq, const float* __restrict__ wrk,
    const float* __restrict__ wo)
{
    int i = blockIdx.x * 256 + threadIdx.x;
    const int A = 393216, B = 786432, C = 2883584;
    if      (i < A) sbody1(wrq, g_wh + (size_t)CRQ * EDIM, i);
    else if (i < B) sbody1(wrk, g_wh + (size_t)CRK * EDIM, i - A);
    else if (i < C) sbody1(wo,  g_woh, i - B);
}

// ---------------- shared machinery ----------------
#define GEMM_PREAMBLE                                                           \
    extern __shared__ __align__(1024) char dsm[];                               \
    const uint32_t sb = smem_u32(dsm);                                          \
    const int tid = threadIdx.x;                                                \
    const int l = tid & 31, wid = tid >> 5;                                     \
    const int cch = tid & 7;                                                    \
    const int akh = (l >> 4);                                                   \
    const int bkh = (l >> 3) & 1;                                               \
    const int lsw = l & 7;

#define LOAD128(base, P, ld, step) do {                                         \
    const __half* G = (P) + (size_t)(step) * 64;                                \
    _Pragma("unroll")                                                           \
    for (int it = 0; it < 4; it++) {                                            \
        int row = (tid >> 3) + 32 * it;                                         \
        uint32_t sw = row * 128u + 16u * (cch ^ (row & 7));                     \
        cpa16((base) + sw, G + (size_t)row * (ld) + cch * 8);                   \
    } } while (0)

#define LOAD64(base, P, ld, step) do {                                          \
    const __half* G = (P) + (size_t)(step) * 64;                                \
    _Pragma("unroll")                                                           \
    for (int it = 0; it < 2; it++) {                                            \
        int row = (tid >> 3) + 32 * it;                                         \
        uint32_t sw = row * 128u + 16u * (cch ^ (row & 7));                     \
        cpa16((base) + sw, G + (size_t)row * (ld) + cch * 8);                   \
    } } while (0)

#define INNER_128(Ab, Bb)                                                       \
    _Pragma("unroll")                                                           \
    for (int kk = 0; kk < 4; kk++) {                                            \
        uint32_t af[4][4], bf[4][2];                                            \
        _Pragma("unroll")                                                       \
        for (int tm = 0; tm < 4; tm++)                                          \
            ldm_x4(af[tm][0], af[tm][1], af[tm][2], af[tm][3],                  \
                   (Ab) + (uint32_t)(ar + tm * 16) * 128u + 16u * (((kk << 1) + akh) ^ lsw)); \
        _Pragma("unroll")                                                       \
        for (int np = 0; np < 2; np++) {                                        \
            uint32_t r0, r1, r2, r3;                                            \
            ldm_x4(r0, r1, r2, r3,                                              \
                   (Bb) + (uint32_t)(br + np * 16) * 128u + 16u * (((kk << 1) + bkh) ^ lsw)); \
            bf[2*np][0] = r0; bf[2*np][1] = r1; bf[2*np+1][0] = r2; bf[2*np+1][1] = r3; \
        }                                                                       \
        _Pragma("unroll")                                                       \
        for (int tm = 0; tm < 4; tm++)                                          \
            _Pragma("unroll")                                                   \
            for (int tn = 0; tn < 4; tn++) mma_f16(acc[tm][tn], af[tm], bf[tn]); \
    }

// ---------------- 2-product fp16 GEMM: C = (Ah+Al) @ Bh^T ----------------
// CTA 64x128, stage raw K=64: AH 8KB @0, AL 8KB @8192, B 16KB @16384; 2 stages.
__global__ __launch_bounds__(256, 3) void gemm2(
    const __half* __restrict__ Ah, const __half* __restrict__ Al,
    const __half* __restrict__ Bh,
    float* __restrict__ C, int ldc, int K)
{
    GEMM_PREAMBLE
    const int wm = wid & 1, wn = wid >> 1;
    const int m0 = blockIdx.y << 6, n0 = blockIdx.x << 7;
    const int steps = K >> 6;
    const __half* Ah_ = Ah + (size_t)m0 * K;
    const __half* Al_ = Al + (size_t)m0 * K;
    const __half* Bh_ = Bh + (size_t)n0 * K;

    float acc[2][4][4];
#pragma unroll
    for (int i = 0; i < 2; i++)
#pragma unroll
        for (int j = 0; j < 4; j++)
#pragma unroll
            for (int r = 0; r < 4; r++) acc[i][j][r] = 0.f;

    const int ar = wm * 32 + (l & 7) + (l & 8);
    const int br = wn * 32 + (l & 7) + 8 * (l >> 4);

    LOAD64(sb, Ah_, K, 0); LOAD64(sb + 8192u, Al_, K, 0);
    LOAD128(sb + 16384u, Bh_, K, 0); cp_commit();

    for (int s = 0; s < steps; s++) {
        cp_wait<0>();
        __syncthreads();
        if (s + 1 < steps) {
            uint32_t b2 = sb + ((s + 1) & 1) * 32768u;
            LOAD64(b2, Ah_, K, s + 1); LOAD64(b2 + 8192u, Al_, K, s + 1);
            LOAD128(b2 + 16384u, Bh_, K, s + 1); cp_commit();
        }
        const uint32_t Ast = sb + (s & 1) * 32768u;
        const uint32_t Bst = Ast + 16384u;
#pragma unroll
        for (int ch = 0; ch < 2; ch++) {
            const uint32_t Ab = Ast + ch * 8192u;
#pragma unroll
            for (int kk = 0; kk < 4; kk++) {
                uint32_t af[2][4], bf[4][2];
#pragma unroll
                for (int tm = 0; tm < 2; tm++)
                    ldm_x4(af[tm][0], af[tm][1], af[tm][2], af[tm][3],
                           Ab + (uint32_t)(ar + tm * 16) * 128u + 16u * (((kk << 1) + akh) ^ lsw));
#pragma unroll
                for (int np = 0; np < 2; np++) {
                    uint32_t r0, r1, r2, r3;
                    ldm_x4(r0, r1, r2, r3,
                           Bst + (uint32_t)(br + np * 16) * 128u + 16u * (((kk << 1) + bkh) ^ lsw));
                    bf[2*np][0] = r0; bf[2*np][1] = r1; bf[2*np+1][0] = r2; bf[2*np+1][1] = r3;
                }
#pragma unroll
                for (int tm = 0; tm < 2; tm++)
#pragma unroll
                    for (int tn = 0; tn < 4; tn++) mma_f16(acc[tm][tn], af[tm], bf[tn]);
            }
        }
    }
    const int er = m0 + wm * 32 + (l >> 2);
    const int ec = n0 + wn * 32 + 2 * (l & 3);
#pragma unroll
    for (int tm = 0; tm < 2; tm++)
#pragma unroll
        for (int tn = 0; tn < 4; tn++) {
            float* p0 = C + (size_t)(er + tm * 16) * ldc + ec + tn * 8;
            float* p1 = C + (size_t)(er + tm * 16 + 8) * ldc + ec + tn * 8;
            *(float2*)p0 = make_float2(acc[tm][tn][0], acc[tm][tn][1]);
            *(float2*)p1 = make_float2(acc[tm][tn][2], acc[tm][tn][3]);
        }
}

// ---------------- scores on tensor cores (fp16, KQ=320) ----------------
__global__ __launch_bounds__(256) void scores_mma()
{
    GEMM_PREAMBLE
    const int wm = wid & 1, wn = wid >> 1;
    const int h = blockIdx.y, idx = blockIdx.x;
    int ti = (int)((sqrtf(8.f * idx + 1.f) - 1.f) * 0.5f);
    while ((ti + 1) * (ti + 2) / 2 <= idx) ti++;
    while (ti * (ti + 1) / 2 > idx) ti--;
    const int tj = idx - ti * (ti + 1) / 2;
    const int i0 = ti << 7, j0 = tj << 7;
    const __half* Ab_ = g_qa + ((size_t)h * SDIM + i0) * KQ;
    const __half* Bb_ = g_kb + ((size_t)h * SDIM + j0) * KQ;
    const int steps = KQ >> 6;   // 5

    float acc[4][4][4];
#pragma unroll
    for (int i = 0; i < 4; i++)
#pragma unroll
        for (int j = 0; j < 4; j++)
#pragma unroll
            for (int r = 0; r < 4; r++) acc[i][j][r] = 0.f;
    const int ar = wm * 64 + (l & 7) + (l & 8);
    const int br = wn * 32 + (l & 7) + 8 * (l >> 4);

    LOAD128(sb, Ab_, KQ, 0); LOAD128(sb + 16384u, Bb_, KQ, 0); cp_commit();
    LOAD128(sb + 32768u, Ab_, KQ, 1); LOAD128(sb + 49152u, Bb_, KQ, 1); cp_commit();

    for (int s = 0; s < steps; s++) {
        cp_wait<1>();
        __syncthreads();
        if (s + 2 < steps) {
            uint32_t b2 = sb + ((s + 2) % 3) * 32768u;
            LOAD128(b2, Ab_, KQ, s + 2); LOAD128(b2 + 16384u, Bb_, KQ, s + 2);
        }
        cp_commit();
        const uint32_t Ab = sb + (s % 3) * 32768u;
        const uint32_t Bb = Ab + 16384u;
        INNER_128(Ab, Bb)
    }
    const int er = i0 + wm * 64 + (l >> 2);
    const int ec = j0 + wn * 32 + 2 * (l & 3);
#pragma unroll
    for (int tm = 0; tm < 4; tm++)
#pragma unroll
        for (int tn = 0; tn < 4; tn++) {
            int r0 = er + tm * 16, r1 = r0 + 8, c = ec + tn * 8;
            float* p0 = g_sc + ((size_t)h * SDIM + r0) * SDIM + c;
            float* p1 = g_sc + ((size_t)h * SDIM + r1) * SDIM + c;
            *(float2*)p0 = make_float2(c     <= r0 ? acc[tm][tn][0] : 0.f,
                                       c + 1 <= r0 ? acc[tm][tn][1] : 0.f);
            *(float2*)p1 = make_float2(c     <= r1 ? acc[tm][tn][2] : 0.f,
                                       c + 1 <= r1 ? acc[tm][tn][3] : 0.f);
        }
}

// ---------------- rowstat ----------------
__global__ __launch_bounds__(256) void rowstat()
{
    const int i = blockIdx.x, h = blockIdx.y;
    const int len = i + 1;
    const float* row = g_sc + ((size_t)h * SDIM + i) * SDIM;
    __shared__ float buf[SDIM];
    __shared__ float red[8];
    const int tid = threadIdx.x;

    float m = -3.4e38f;
    for (int j = tid; j < len; j += 256) { float v = row[j]; buf[j] = v; m = fmaxf(m, v); }
#pragma unroll
    for (int o = 16; o; o >>= 1) m = fmaxf(m, __shfl_xor_sync(0xffffffffu, m, o));
    if ((tid & 31) == 0) red[tid >> 5] = m;
    __syncthreads();
    m = red[0];
#pragma unroll
    for (int q = 1; q < 8; q++) m = fmaxf(m, red[q]);
    __syncthreads();

    float sum = 0.f;
    for (int j = tid; j < len; j += 256) sum += __expf(buf[j] - m);
#pragma unroll
    for (int o = 16; o; o >>= 1) sum += __shfl_xor_sync(0xffffffffu, sum, o);
    if ((tid & 31) == 0) red[tid >> 5] = sum;
    __syncthreads();
    if (tid == 0) {
        sum = red[0] + red[1] + red[2] + red[3] + red[4] + red[5] + red[6] + red[7];
        g_rm[h * SDIM + i] = m;
        g_ri[h * SDIM + i] = 1.f / sum;
    }
}

// ---------------- AV fused fp16: 2 products (attn hi/lo x Vh) ----------------
// smem: A 2 bufs x (AH 8KB + AL 8KB) @0; B (Vh) 2 bufs x 16KB @32768. 64KB total.
__global__ __launch_bounds__(256) void av_mma()
{
    extern __shared__ __align__(1024) char dsm[];
    const uint32_t sb = smem_u32(dsm);
    const int tid = threadIdx.x;
    const int l = tid & 31, wid = tid >> 5;
    const int cch = tid & 7;
    const int akh = (l >> 4);
    const int bkh = (l >> 3) & 1;
    const int lsw = l & 7;
    const int wm = wid & 1, wn = wid >> 1;
    const int h = blockIdx.y;
    const __half* Vh_ = g_vth + (size_t)(h >> 2) * DH * SDIM;

    const int ar = wm * 32 + (l & 7) + (l & 8);
    const int br = wn * 32 + (l & 7) + 8 * (l >> 4);
    const int pr_ = tid >> 2;
    const int pc0 = (tid & 3) << 4;

    for (int half = 0; half < 2; half++) {
        const int mt = half ? 31 - (int)blockIdx.x : (int)blockIdx.x;
        const int m0 = mt << 6;
        const int njt = mt + 1;

        float acc[2][4][4];
#pragma unroll
        for (int i = 0; i < 2; i++)
#pragma unroll
            for (int j = 0; j < 4; j++)
#pragma unroll
                for (int r = 0; r < 4; r++) acc[i][j][r] = 0.f;

        LOAD128(sb + 32768u, Vh_, SDIM, 0);
        cp_commit();

        const int grow = m0 + pr_;
        const float mrow = g_rm[h * SDIM + grow];
        const float irow = g_ri[h * SDIM + grow];
        const float* srow0 = g_sc + ((size_t)h * SDIM + grow) * SDIM + pc0;

        for (int jt = 0; jt < njt; jt++) {
            const int buf = jt & 1;
            const uint32_t AHo = buf * 16384u;
            const uint32_t ALo = AHo + 8192u;
            const uint32_t BH = sb + 32768u + buf * 16384u;
            {
                const float* srow = srow0 + jt * 64;
                float4 s0 = *(const float4*)(srow);
                float4 s1 = *(const float4*)(srow + 4);
                float4 s2 = *(const float4*)(srow + 8);
                float4 s3 = *(const float4*)(srow + 12);
                float sv[16] = {s0.x,s0.y,s0.z,s0.w, s1.x,s1.y,s1.z,s1.w,
                                s2.x,s2.y,s2.z,s2.w, s3.x,s3.y,s3.z,s3.w};
#pragma unroll
                for (int p = 0; p < 8; p++) {
                    int c = pc0 + 2 * p;
                    int gc = jt * 64 + c;
                    float p0 = (gc     <= grow) ? __expf(sv[2*p]   - mrow) * irow : 0.f;
                    float p1 = (gc + 1 <= grow) ? __expf(sv[2*p+1] - mrow) * irow : 0.f;
                    uint32_t H0, L0, H1, L1;
                    fold2h(p0, H0, L0); fold2h(p1, H1, L1);
                    uint32_t byte = (uint32_t)pr_ * 128u
                                  + ((((c >> 3) ^ (pr_ & 7)) & 7) << 4) + ((c & 7) << 1);
                    *(uint32_t*)(dsm + AHo + byte) = H0 | (H1 << 16);
                    *(uint32_t*)(dsm + ALo + byte) = L0 | (L1 << 16);
                }
            }
            cp_wait<0>();
            __syncthreads();
            if (jt + 1 < njt) {
                uint32_t B2 = sb + 32768u + (buf ^ 1) * 16384u;
                LOAD128(B2, Vh_, SDIM, jt + 1);
                cp_commit();
            }
#pragma unroll
            for (int ch = 0; ch < 2; ch++) {
                const uint32_t Ab = sb + ((ch == 0) ? AHo : ALo);
#pragma unroll
                for (int kk = 0; kk < 4; kk++) {
                    uint32_t af[2][4], bf[4][2];
#pragma unroll
                    for (int tm = 0; tm < 2; tm++)
                        ldm_x4(af[tm][0], af[tm][1], af[tm][2], af[tm][3],
                               Ab + (uint32_t)(ar + tm * 16) * 128u + 16u * (((kk << 1) + akh) ^ lsw));
#pragma unroll
                    for (int np = 0; np < 2; np++) {
                        uint32_t r0, r1, r2, r3;
                        ldm_x4(r0, r1, r2, r3,
                               BH + (uint32_t)(br + np * 16) * 128u + 16u * (((kk << 1) + bkh) ^ lsw));
                        bf[2*np][0] = r0; bf[2*np][1] = r1; bf[2*np+1][0] = r2; bf[2*np+1][1] = r3;
                    }
#pragma unroll
                    for (int tm = 0; tm < 2; tm++)
#pragma unroll
                        for (int tn = 0; tn < 4; tn++) mma_f16(acc[tm][tn], af[tm], bf[tn]);
                }
            }
        }
        const int er = m0 + wm * 32 + (l >> 2);
        const int ecl = wn * 32 + 2 * (l & 3);
#pragma unroll
        for (int tm = 0; tm < 2; tm++)
#pragma unroll
            for (int tn = 0; tn < 4; tn++) {
                int c = h * DH + ecl + tn * 8;
                int r0 = er + tm * 16, r1 = r0 + 8;
#pragma unroll
                for (int rr = 0; rr < 2; rr++) {
                    int row = rr ? r1 : r0;
                    float v0 = acc[tm][tn][rr ? 2 : 0];
                    float v1 = acc[tm][tn][rr ? 3 : 1];
                    uint32_t H0, L0, H1, L1;
                    fold2h(v0, H0, L0); fold2h(v1, H1, L1);
                    ((uint32_t*)g_aoh)[(size_t)row * (EDIM/2) + (c >> 1)] = H0 | (H1 << 16);
                    ((uint32_t*)g_aol)[(size_t)row * (EDIM/2) + (c >> 1)] = L0 | (L1 << 16);
                }
            }
        __syncthreads();
    }
}

// ---------------- fused RMSNorm + RoPE + fold into qa (fp16) ----------------
__global__ __launch_bounds__(128) void norm_fill_qa(
    const float* __restrict__ w, const float* __restrict__ gscale)
{
    const int s = blockIdx.x, h = blockIdx.y, d = threadIdx.x;
    float v = g_pr[(size_t)s * NOUT + CQ + h * DH + d];
    float ss = v * v;
#pragma unroll
    for (int o = 16; o; o >>= 1) ss += __shfl_xor_sync(0xffffffffu, ss, o);
    __shared__ float r4[4];
    __shared__ float sh[DH];
    if ((d & 31) == 0) r4[d >> 5] = ss;
    __syncthreads();
    float nv = v * rsqrtf((r4[0]+r4[1]+r4[2]+r4[3]) * (1.f / DH) + 1e-6f) * w[d];
    sh[d] = nv;
    __syncthreads();
    const int dm = d & 63;
    float f = 1.f / powf(10000.f, (float)(2 * dm) * (1.f / DH));
    float cs, sn; sincosf((float)s * f, &sn, &cs);
    float rot = (d < 64) ? -sh[d + 64] : sh[d - 64];
    float qs = (nv * cs + rot * sn) * 0.08838834764831845f;

    __half* row = g_qa + ((size_t)h * SDIM + s) * KQ;
    uint32_t H, L; fold2h(qs, H, L);
    row[d]       = __ushort_as_half((unsigned short)H);
    row[128 + d] = __ushort_as_half((unsigned short)L);
    if (d < 32) {
        float bv = 0.f;
        if (h < NHG) bv = gscale[h] * (h < NSYM ? 0.5f : 1.f)
                         * g_pr[(size_t)s * NOUT + CRQ + h * RDIM + d];
        row[256 + d] = __float2half_rn(bv);
    } else if (d < 64) {
        int r = d - 32;
        float bv = 0.f;
        if (h < NSYM) bv = gscale[h] * 0.5f * g_pr[(size_t)s * NOUT + CRK + h * RDIM + r];
        row[288 + r] = __float2half_rn(bv);
    }
}

// ---------------- fused RMSNorm + RoPE + fold into kb (fp16) ----------------
__global__ __launch_bounds__(128) void norm_fill_kb(const float* __restrict__ w)
{
    const int s = blockIdx.x, kvh = blockIdx.y, d = threadIdx.x;
    float v = g_pr[(size_t)s * NOUT + CK + kvh * DH + d];
    float ss = v * v;
#pragma unroll
    for (int o = 16; o; o >>= 1) ss += __shfl_xor_sync(0xffffffffu, ss, o);
    __shared__ float r4[4];
    __shared__ float sh[DH];
    if ((d & 31) == 0) r4[d >> 5] = ss;
    __syncthreads();
    float nv = v * rsqrtf((r4[0]+r4[1]+r4[2]+r4[3]) * (1.f / DH) + 1e-6f) * w[d];
    sh[d] = nv;
    __syncthreads();
    const int dm = d & 63;
    float f = 1.f / powf(10000.f, (float)(2 * dm) * (1.f / DH));
    float cs, sn; sincosf((float)s * f, &sn, &cs);
    float rot = (d < 64) ? -sh[d + 64] : sh[d - 64];
    float kf = nv * cs + rot * sn;
    __half kh = __float2half_rn(kf);

#pragma unroll
    for (int e = 0; e < 4; e++) {
        int h = kvh * 4 + e;
        __half* row = g_kb + ((size_t)h * SDIM + s) * KQ;
        row[d]       = kh;
        row[128 + d] = kh;     // duplicated for the qL chunk
        if (d < 32) {
            float bv = (h < NHG) ? g_pr[(size_t)s * NOUT + CRK + h * RDIM + d] : 0.f;
            row[256 + d] = __float2half_rn(bv);
        } else if (d < 64) {
            int r = d - 32;
            float bv = (h < NSYM) ? g_pr[(size_t)s * NOUT + CRQ + h * RDIM + r] : 0.f;
            row[288 + r] = __float2half_rn(bv);
        }
    }
}

// ---------------- fill vth (smem transpose, fp16 single) ----------------
__global__ __launch_bounds__(128) void fill_vh()
{
    __shared__ float sm[64][129];
    const int jb = blockIdx.x, kvh = blockIdx.y;
    const int tid = threadIdx.x;
    for (int jj = 0; jj < 64; jj++)
        sm[jj][tid] = g_pr[(size_t)(jb * 64 + jj) * NOUT + CV + kvh * DH + tid];
    __syncthreads();
    const int w = tid >> 5, ln = tid & 31;
    for (int d = w; d < DH; d += 4) {
        __half h0 = __float2half_rn(sm[2*ln][d]);
        __half h1 = __float2half_rn(sm[2*ln+1][d]);
        uint32_t* oh = (uint32_t*)(g_vth + (size_t)(kvh * DH + d) * SDIM + jb * 64);
        oh[ln] = (uint32_t)__half_as_ushort(h0) | ((uint32_t)__half_as_ushort(h1) << 16);
    }
}

// ---------------- Host ----------------
extern "C" void kernel_launch(void* const* d_in, const int* in_sizes, int n_in,
                              void* d_out, int out_size)
{
    const float* x   = (const float*)d_in[0];
    const float* Wq  = (const float*)d_in[1];
    const float* Wk  = (const float*)d_in[2];
    const float* Wv  = (const float*)d_in[3];
    const float* Wo  = (const float*)d_in[4];
    const float* qnw = (const float*)d_in[5];
    const float* knw = (const float*)d_in[6];
    const float* Wrq = (const float*)d_in[7];
    const float* Wrk = (const float*)d_in[8];
    const float* gsc = (const float*)d_in[9];
    float* out = (float*)d_out;

    float* pr;
    __half *xh, *xl, *wh, *woh, *aoh, *aol;
    cudaGetSymbolAddress((void**)&pr,  g_pr);
    cudaGetSymbolAddress((void**)&xh,  g_xh);
    cudaGetSymbolAddress((void**)&xl,  g_xl);
    cudaGetSymbolAddress((void**)&wh,  g_wh);
    cudaGetSymbolAddress((void**)&woh, g_woh);
    cudaGetSymbolAddress((void**)&aoh, g_aoh);
    cudaGetSymbolAddress((void**)&aol, g_aol);

    cudaFuncSetAttribute(gemm2,      cudaFuncAttributeMaxDynamicSharedMemorySize, 65536);
    cudaFuncSetAttribute(scores_mma, cudaFuncAttributeMaxDynamicSharedMemorySize, 98304);
    cudaFuncSetAttribute(av_mma,     cudaFuncAttributeMaxDynamicSharedMemorySize, 65536);

    split_x<<<8192, 256>>>(x, xh, xl, SDIM*EDIM/2);
    split_w1<<<12288, 256>>>(Wq, Wk, Wv);
    split_w2<<<11264, 256>>>(Wrq, Wrk, Wo);

    // index 3 under ncu: merged projection GEMM (fp16, 2 products)
    gemm2<<<dim3(NOUT/128, SDIM/64), 256, 65536>>>(xh, xl, wh, pr, NOUT, EDIM);

    norm_fill_qa<<<dim3(SDIM, NH),  128>>>(qnw, gsc);
    norm_fill_kb<<<dim3(SDIM, NKV), 128>>>(knw);
    fill_vh<<<dim3(SDIM/64, NKV), 128>>>();

    scores_mma<<<dim3(136, NH), 256, 98304>>>();
    rowstat<<<dim3(SDIM, NH), 256>>>();
    av_mma<<<dim3(16, NH), 256, 65536>>>();

    gemm2<<<dim3(EDIM/128, SDIM/64), 256, 65536>>>(aoh, aol, woh, out, EDIM, EDIM);
}

// round 12
// speedup vs baseline: 1.7360x; 1.1908x over previous
#include <cuda_runtime.h>
#include <cuda_fp16.h>
#include <math.h>
#include <stdint.h>

#define SDIM 2048
#define EDIM 2048
#define NH   16
#define NKV  4
#define DH   128
#define NHG  12
#define RDIM 32
#define NSYM 4
#define NOUT 3840
#define CQ   0
#define CK   2048
#define CV   2560
#define CRQ  3072
#define CRK  3456
#define KQ   320

static __device__ float g_pr[SDIM*NOUT];
static __device__ float g_sc[(size_t)NH*SDIM*SDIM];   // holds exp(scores), masked=0
static __device__ float g_rs[NH*SDIM];                // row sums of exp
static __device__ __half g_xh [SDIM*EDIM];
static __device__ __half g_xl [SDIM*EDIM];
static __device__ __half g_wh [(size_t)NOUT*EDIM];
static __device__ __half g_woh[(size_t)EDIM*EDIM];
static __device__ __half g_aoh[(size_t)SDIM*EDIM];
static __device__ __half g_aol[(size_t)SDIM*EDIM];
static __device__ __half g_qa [(size_t)NH*SDIM*KQ];
static __device__ __half g_kb [(size_t)NH*SDIM*KQ];
static __device__ __half g_vth[(size_t)NKV*DH*SDIM];

// ---------------- PTX helpers ----------------
__device__ __forceinline__ uint32_t smem_u32(const void* p) {
    uint32_t a;
    asm("{ .reg .u64 t; cvta.to.shared.u64 t, %1; cvt.u32.u64 %0, t; }" : "=r"(a) : "l"(p));
    return a;
}
__device__ __forceinline__ void cpa16(uint32_t d, const void* g) {
    asm volatile("cp.async.cg.shared.global [%0], [%1], 16;" :: "r"(d), "l"(g));
}
__device__ __forceinline__ void cp_commit() { asm volatile("cp.async.commit_group;" ::: "memory"); }
template<int N> __device__ __forceinline__ void cp_wait() {
    asm volatile("cp.async.wait_group %0;" :: "n"(N) : "memory");
}
__device__ __forceinline__ void ldm_x4(uint32_t& r0, uint32_t& r1, uint32_t& r2, uint32_t& r3,
                                       uint32_t addr) {
    asm volatile("ldmatrix.sync.aligned.m8n8.x4.shared.b16 {%0,%1,%2,%3}, [%4];"
                 : "=r"(r0), "=r"(r1), "=r"(r2), "=r"(r3) : "r"(addr));
}
__device__ __forceinline__ void mma_f16(float* d, const uint32_t* a, const uint32_t* b) {
    asm volatile("mma.sync.aligned.m16n8k16.row.col.f32.f16.f16.f32 "
                 "{%0,%1,%2,%3}, {%4,%5,%6,%7}, {%8,%9}, {%0,%1,%2,%3};"
                 : "+f"(d[0]), "+f"(d[1]), "+f"(d[2]), "+f"(d[3])
                 : "r"(a[0]), "r"(a[1]), "r"(a[2]), "r"(a[3]), "r"(b[0]), "r"(b[1]));
}
__device__ __forceinline__ void fold2h(float v, uint32_t& H, uint32_t& L) {
    __half h = __float2half_rn(v);
    __half l = __float2half_rn(v - __half2float(h));
    H = __half_as_ushort(h); L = __half_as_ushort(l);
}
__device__ __forceinline__ void sbody2(const float* s, __half* dh, __half* dl, int i) {
    float2 v = ((const float2*)s)[i];
    uint32_t H0, L0, H1, L1;
    fold2h(v.x, H0, L0); fold2h(v.y, H1, L1);
    ((uint32_t*)dh)[i] = H0 | (H1 << 16);
    ((uint32_t*)dl)[i] = L0 | (L1 << 16);
}
__device__ __forceinline__ void sbody1(const float* s, __half* dh, int i) {
    float2 v = ((const float2*)s)[i];
    __half h0 = __float2half_rn(v.x), h1 = __float2half_rn(v.y);
    ((uint32_t*)dh)[i] = (uint32_t)__half_as_ushort(h0)
                       | ((uint32_t)__half_as_ushort(h1) << 16);
}

__global__ __launch_bounds__(256) void split_x(
    const float* __restrict__ s, __half* __restrict__ dh,
    __half* __restrict__ dl, int npairs)
{
    int i = blockIdx.x * 256 + threadIdx.x;
    if (i < npairs) sbody2(s, dh, dl, i);
}
__global__ __launch_bounds__(256) void split_w1(
    const float* __restrict__ wq, const float* __restrict__ wk,
    const float* __restrict__ wv)
{
    int i = blockIdx.x * 256 + threadIdx.x;
    const int A = 2097152, B = 2621440, C = 3145728;
    if      (i < A) sbody1(wq, g_wh + (size_t)CQ * EDIM, i);
    else if (i < B) sbody1(wk, g_wh + (size_t)CK * EDIM, i - A);
    else if (i < C) sbody1(wv, g_wh + (size_t)CV * EDIM, i - B);
}
__global__ __launch_bounds__(256) void split_w2(
    const float* __restrict__ wrq, const float* __restrict__ wrk,
    const float* __restrict__ wo)
{
    int i = blockIdx.x * 256 + threadIdx.x;
    const int A = 393216, B = 786432, C = 2883584;
    if      (i < A) sbody1(wrq, g_wh + (size_t)CRQ * EDIM, i);
    else if (i < B) sbody1(wrk, g_wh + (size_t)CRK * EDIM, i - A);
    else if (i < C) sbody1(wo,  g_woh, i - B);
}

// ---------------- shared machinery ----------------
#define GEMM_PREAMBLE                                                           \
    extern __shared__ __align__(1024) char dsm[];                               \
    const uint32_t sb = smem_u32(dsm);                                          \
    const int tid = threadIdx.x;                                                \
    const int l = tid & 31, wid = tid >> 5;                                     \
    const int cch = tid & 7;                                                    \
    const int akh = (l >> 4);                                                   \
    const int bkh = (l >> 3) & 1;                                               \
    const int lsw = l & 7;

#define LOAD128(base, P, ld, step) do {                                         \
    const __half* G = (P) + (size_t)(step) * 64;                                \
    _Pragma("unroll")                                                           \
    for (int it = 0; it < 4; it++) {                                            \
        int row = (tid >> 3) + 32 * it;                                         \
        uint32_t sw = row * 128u + 16u * (cch ^ (row & 7));                     \
        cpa16((base) + sw, G + (size_t)row * (ld) + cch * 8);                   \
    } } while (0)

#define LOAD64(base, P, ld, step) do {                                          \
    const __half* G = (P) + (size_t)(step) * 64;                                \
    _Pragma("unroll")                                                           \
    for (int it = 0; it < 2; it++) {                                            \
        int row = (tid >> 3) + 32 * it;                                         \
        uint32_t sw = row * 128u + 16u * (cch ^ (row & 7));                     \
        cpa16((base) + sw, G + (size_t)row * (ld) + cch * 8);                   \
    } } while (0)

#define INNER_128(Ab, Bb)                                                       \
    _Pragma("unroll")                                                           \
    for (int kk = 0; kk < 4; kk++) {                                            \
        uint32_t af[4][4], bf[4][2];                                            \
        _Pragma("unroll")                                                       \
        for (int tm = 0; tm < 4; tm++)                                          \
            ldm_x4(af[tm][0], af[tm][1], af[tm][2], af[tm][3],                  \
                   (Ab) + (uint32_t)(ar + tm * 16) * 128u + 16u * (((kk << 1) + akh) ^ lsw)); \
        _Pragma("unroll")                                                       \
        for (int np = 0; np < 2; np++) {                                        \
            uint32_t r0, r1, r2, r3;                                            \
            ldm_x4(r0, r1, r2, r3,                                              \
                   (Bb) + (uint32_t)(br + np * 16) * 128u + 16u * (((kk << 1) + bkh) ^ lsw)); \
            bf[2*np][0] = r0; bf[2*np][1] = r1; bf[2*np+1][0] = r2; bf[2*np+1][1] = r3; \
        }                                                                       \
        _Pragma("unroll")                                                       \
        for (int tm = 0; tm < 4; tm++)                                          \
            _Pragma("unroll")                                                   \
            for (int tn = 0; tn < 4; tn++) mma_f16(acc[tm][tn], af[tm], bf[tn]); \
    }

// ---------------- 2-product fp16 GEMM: shared-B inner loop ----------------
// CTA 64x128, stage raw K=64: AH 8KB @0, AL 8KB @8192, B 16KB @16384; 2 stages.
__global__ __launch_bounds__(256, 3) void gemm2(
    const __half* __restrict__ Ah, const __half* __restrict__ Al,
    const __half* __restrict__ Bh,
    float* __restrict__ C, int ldc, int K)
{
    GEMM_PREAMBLE
    const int wm = wid & 1, wn = wid >> 1;
    const int m0 = blockIdx.y << 6, n0 = blockIdx.x << 7;
    const int steps = K >> 6;
    const __half* Ah_ = Ah + (size_t)m0 * K;
    const __half* Al_ = Al + (size_t)m0 * K;
    const __half* Bh_ = Bh + (size_t)n0 * K;

    float acc[2][4][4];
#pragma unroll
    for (int i = 0; i < 2; i++)
#pragma unroll
        for (int j = 0; j < 4; j++)
#pragma unroll
            for (int r = 0; r < 4; r++) acc[i][j][r] = 0.f;

    const int ar = wm * 32 + (l & 7) + (l & 8);
    const int br = wn * 32 + (l & 7) + 8 * (l >> 4);

    LOAD64(sb, Ah_, K, 0); LOAD64(sb + 8192u, Al_, K, 0);
    LOAD128(sb + 16384u, Bh_, K, 0); cp_commit();

    for (int s = 0; s < steps; s++) {
        cp_wait<0>();
        __syncthreads();
        if (s + 1 < steps) {
            uint32_t b2 = sb + ((s + 1) & 1) * 32768u;
            LOAD64(b2, Ah_, K, s + 1); LOAD64(b2 + 8192u, Al_, K, s + 1);
            LOAD128(b2 + 16384u, Bh_, K, s + 1); cp_commit();
        }
        const uint32_t Ast = sb + (s & 1) * 32768u;
        const uint32_t Bst = Ast + 16384u;
#pragma unroll
        for (int kk = 0; kk < 4; kk++) {
            uint32_t bf[4][2], afh[2][4], afl[2][4];
#pragma unroll
            for (int np = 0; np < 2; np++) {
                uint32_t r0, r1, r2, r3;
                ldm_x4(r0, r1, r2, r3,
                       Bst + (uint32_t)(br + np * 16) * 128u + 16u * (((kk << 1) + bkh) ^ lsw));
                bf[2*np][0] = r0; bf[2*np][1] = r1; bf[2*np+1][0] = r2; bf[2*np+1][1] = r3;
            }
#pragma unroll
            for (int tm = 0; tm < 2; tm++) {
                ldm_x4(afh[tm][0], afh[tm][1], afh[tm][2], afh[tm][3],
                       Ast + (uint32_t)(ar + tm * 16) * 128u + 16u * (((kk << 1) + akh) ^ lsw));
                ldm_x4(afl[tm][0], afl[tm][1], afl[tm][2], afl[tm][3],
                       Ast + 8192u + (uint32_t)(ar + tm * 16) * 128u + 16u * (((kk << 1) + akh) ^ lsw));
            }
#pragma unroll
            for (int tm = 0; tm < 2; tm++)
#pragma unroll
                for (int tn = 0; tn < 4; tn++) mma_f16(acc[tm][tn], afh[tm], bf[tn]);
#pragma unroll
            for (int tm = 0; tm < 2; tm++)
#pragma unroll
                for (int tn = 0; tn < 4; tn++) mma_f16(acc[tm][tn], afl[tm], bf[tn]);
        }
    }
    const int er = m0 + wm * 32 + (l >> 2);
    const int ec = n0 + wn * 32 + 2 * (l & 3);
#pragma unroll
    for (int tm = 0; tm < 2; tm++)
#pragma unroll
        for (int tn = 0; tn < 4; tn++) {
            float* p0 = C + (size_t)(er + tm * 16) * ldc + ec + tn * 8;
            float* p1 = C + (size_t)(er + tm * 16 + 8) * ldc + ec + tn * 8;
            *(float2*)p0 = make_float2(acc[tm][tn][0], acc[tm][tn][1]);
            *(float2*)p1 = make_float2(acc[tm][tn][2], acc[tm][tn][3]);
        }
}

// ---------------- scores: mma + fused exp + row-sum atomics ----------------
__global__ __launch_bounds__(256) void scores_mma()
{
    GEMM_PREAMBLE
    const int wm = wid & 1, wn = wid >> 1;
    const int h = blockIdx.y, idx = blockIdx.x;
    int ti = (int)((sqrtf(8.f * idx + 1.f) - 1.f) * 0.5f);
    while ((ti + 1) * (ti + 2) / 2 <= idx) ti++;
    while (ti * (ti + 1) / 2 > idx) ti--;
    const int tj = idx - ti * (ti + 1) / 2;
    const int i0 = ti << 7, j0 = tj << 7;
    const __half* Ab_ = g_qa + ((size_t)h * SDIM + i0) * KQ;
    const __half* Bb_ = g_kb + ((size_t)h * SDIM + j0) * KQ;
    const int steps = KQ >> 6;   // 5

    float acc[4][4][4];
#pragma unroll
    for (int i = 0; i < 4; i++)
#pragma unroll
        for (int j = 0; j < 4; j++)
#pragma unroll
            for (int r = 0; r < 4; r++) acc[i][j][r] = 0.f;
    const int ar = wm * 64 + (l & 7) + (l & 8);
    const int br = wn * 32 + (l & 7) + 8 * (l >> 4);

    LOAD128(sb, Ab_, KQ, 0); LOAD128(sb + 16384u, Bb_, KQ, 0); cp_commit();
    LOAD128(sb + 32768u, Ab_, KQ, 1); LOAD128(sb + 49152u, Bb_, KQ, 1); cp_commit();

    for (int s = 0; s < steps; s++) {
        cp_wait<1>();
        __syncthreads();
        if (s + 2 < steps) {
            uint32_t b2 = sb + ((s + 2) % 3) * 32768u;
            LOAD128(b2, Ab_, KQ, s + 2); LOAD128(b2 + 16384u, Bb_, KQ, s + 2);
        }
        cp_commit();
        const uint32_t Ab = sb + (s % 3) * 32768u;
        const uint32_t Bb = Ab + 16384u;
        INNER_128(Ab, Bb)
    }
    // epilogue: e = exp(masked s), write e, accumulate row sums
    const int er = i0 + wm * 64 + (l >> 2);
    const int ec = j0 + wn * 32 + 2 * (l & 3);
    float rsum[4][2];
#pragma unroll
    for (int tm = 0; tm < 4; tm++) { rsum[tm][0] = 0.f; rsum[tm][1] = 0.f; }
#pragma unroll
    for (int tm = 0; tm < 4; tm++)
#pragma unroll
        for (int tn = 0; tn < 4; tn++) {
            int r0 = er + tm * 16, r1 = r0 + 8, c = ec + tn * 8;
            float e00 = (c     <= r0) ? __expf(acc[tm][tn][0]) : 0.f;
            float e01 = (c + 1 <= r0) ? __expf(acc[tm][tn][1]) : 0.f;
            float e10 = (c     <= r1) ? __expf(acc[tm][tn][2]) : 0.f;
            float e11 = (c + 1 <= r1) ? __expf(acc[tm][tn][3]) : 0.f;
            float* p0 = g_sc + ((size_t)h * SDIM + r0) * SDIM + c;
            float* p1 = g_sc + ((size_t)h * SDIM + r1) * SDIM + c;
            *(float2*)p0 = make_float2(e00, e01);
            *(float2*)p1 = make_float2(e10, e11);
            rsum[tm][0] += e00 + e01;
            rsum[tm][1] += e10 + e11;
        }
#pragma unroll
    for (int tm = 0; tm < 4; tm++)
#pragma unroll
        for (int rr = 0; rr < 2; rr++) {
            float v = rsum[tm][rr];
            v += __shfl_xor_sync(0xffffffffu, v, 1);
            v += __shfl_xor_sync(0xffffffffu, v, 2);
            if ((l & 3) == 0)
                atomicAdd(&g_rs[h * SDIM + er + tm * 16 + rr * 8], v);
        }
}

// ---------------- AV fused fp16: shared-B inner, p = e/rowsum ----------------
// smem: A 2 bufs x (AH 8KB + AL 8KB) @0; B (Vh) 2 bufs x 16KB @32768. 64KB.
__global__ __launch_bounds__(256) void av_mma()
{
    extern __shared__ __align__(1024) char dsm[];
    const uint32_t sb = smem_u32(dsm);
    const int tid = threadIdx.x;
    const int l = tid & 31, wid = tid >> 5;
    const int cch = tid & 7;
    const int akh = (l >> 4);
    const int bkh = (l >> 3) & 1;
    const int lsw = l & 7;
    const int wm = wid & 1, wn = wid >> 1;
    const int h = blockIdx.y;
    const __half* Vh_ = g_vth + (size_t)(h >> 2) * DH * SDIM;

    const int ar = wm * 32 + (l & 7) + (l & 8);
    const int br = wn * 32 + (l & 7) + 8 * (l >> 4);
    const int pr_ = tid >> 2;
    const int pc0 = (tid & 3) << 4;

    for (int half = 0; half < 2; half++) {
        const int mt = half ? 31 - (int)blockIdx.x : (int)blockIdx.x;
        const int m0 = mt << 6;
        const int njt = mt + 1;

        float acc[2][4][4];
#pragma unroll
        for (int i = 0; i < 2; i++)
#pragma unroll
            for (int j = 0; j < 4; j++)
#pragma unroll
                for (int r = 0; r < 4; r++) acc[i][j][r] = 0.f;

        LOAD128(sb + 32768u, Vh_, SDIM, 0);
        cp_commit();

        const int grow = m0 + pr_;
        const float irow = 1.f / g_rs[h * SDIM + grow];
        const float* srow0 = g_sc + ((size_t)h * SDIM + grow) * SDIM + pc0;

        for (int jt = 0; jt < njt; jt++) {
            const int buf = jt & 1;
            const uint32_t AHo = buf * 16384u;
            const uint32_t ALo = AHo + 8192u;
            const uint32_t BH = sb + 32768u + buf * 16384u;
            {
                const float* srow = srow0 + jt * 64;
                float4 s0 = *(const float4*)(srow);
                float4 s1 = *(const float4*)(srow + 4);
                float4 s2 = *(const float4*)(srow + 8);
                float4 s3 = *(const float4*)(srow + 12);
                float sv[16] = {s0.x,s0.y,s0.z,s0.w, s1.x,s1.y,s1.z,s1.w,
                                s2.x,s2.y,s2.z,s2.w, s3.x,s3.y,s3.z,s3.w};
#pragma unroll
                for (int p = 0; p < 8; p++) {
                    int c = pc0 + 2 * p;
                    float p0 = sv[2*p]   * irow;
                    float p1 = sv[2*p+1] * irow;
                    uint32_t H0, L0, H1, L1;
                    fold2h(p0, H0, L0); fold2h(p1, H1, L1);
                    uint32_t byte = (uint32_t)pr_ * 128u
                                  + ((((c >> 3) ^ (pr_ & 7)) & 7) << 4) + ((c & 7) << 1);
                    *(uint32_t*)(dsm + AHo + byte) = H0 | (H1 << 16);
                    *(uint32_t*)(dsm + ALo + byte) = L0 | (L1 << 16);
                }
            }
            cp_wait<0>();
            __syncthreads();
            if (jt + 1 < njt) {
                uint32_t B2 = sb + 32768u + (buf ^ 1) * 16384u;
                LOAD128(B2, Vh_, SDIM, jt + 1);
                cp_commit();
            }
#pragma unroll
            for (int kk = 0; kk < 4; kk++) {
                uint32_t bf[4][2], afh[2][4], afl[2][4];
#pragma unroll
                for (int np = 0; np < 2; np++) {
                    uint32_t r0, r1, r2, r3;
                    ldm_x4(r0, r1, r2, r3,
                           BH + (uint32_t)(br + np * 16) * 128u + 16u * (((kk << 1) + bkh) ^ lsw));
                    bf[2*np][0] = r0; bf[2*np][1] = r1; bf[2*np+1][0] = r2; bf[2*np+1][1] = r3;
                }
#pragma unroll
                for (int tm = 0; tm < 2; tm++) {
                    ldm_x4(afh[tm][0], afh[tm][1], afh[tm][2], afh[tm][3],
                           sb + AHo + (uint32_t)(ar + tm * 16) * 128u + 16u * (((kk << 1) + akh) ^ lsw));
                    ldm_x4(afl[tm][0], afl[tm][1], afl[tm][2], afl[tm][3],
                           sb + ALo + (uint32_t)(ar + tm * 16) * 128u + 16u * (((kk << 1) + akh) ^ lsw));
                }
#pragma unroll
                for (int tm = 0; tm < 2; tm++)
#pragma unroll
                    for (int tn = 0; tn < 4; tn++) mma_f16(acc[tm][tn], afh[tm], bf[tn]);
#pragma unroll
                for (int tm = 0; tm < 2; tm++)
#pragma unroll
                    for (int tn = 0; tn < 4; tn++) mma_f16(acc[tm][tn], afl[tm], bf[tn]);
            }
        }
        const int er = m0 + wm * 32 + (l >> 2);
        const int ecl = wn * 32 + 2 * (l & 3);
#pragma unroll
        for (int tm = 0; tm < 2; tm++)
#pragma unroll
            for (int tn = 0; tn < 4; tn++) {
                int c = h * DH + ecl + tn * 8;
                int r0 = er + tm * 16, r1 = r0 + 8;
#pragma unroll
                for (int rr = 0; rr < 2; rr++) {
                    int row = rr ? r1 : r0;
                    float v0 = acc[tm][tn][rr ? 2 : 0];
                    float v1 = acc[tm][tn][rr ? 3 : 1];
                    uint32_t H0, L0, H1, L1;
                    fold2h(v0, H0, L0); fold2h(v1, H1, L1);
                    ((uint32_t*)g_aoh)[(size_t)row * (EDIM/2) + (c >> 1)] = H0 | (H1 << 16);
                    ((uint32_t*)g_aol)[(size_t)row * (EDIM/2) + (c >> 1)] = L0 | (L1 << 16);
                }
            }
        __syncthreads();
    }
}

// ---------------- fused RMSNorm + RoPE + fold into qa (fp16) ----------------
__global__ __launch_bounds__(128) void norm_fill_qa(
    const float* __restrict__ w, const float* __restrict__ gscale)
{
    const int s = blockIdx.x, h = blockIdx.y, d = threadIdx.x;
    float v = g_pr[(size_t)s * NOUT + CQ + h * DH + d];
    float ss = v * v;
#pragma unroll
    for (int o = 16; o; o >>= 1) ss += __shfl_xor_sync(0xffffffffu, ss, o);
    __shared__ float r4[4];
    __shared__ float sh[DH];
    if ((d & 31) == 0) r4[d >> 5] = ss;
    __syncthreads();
    float nv = v * rsqrtf((r4[0]+r4[1]+r4[2]+r4[3]) * (1.f / DH) + 1e-6f) * w[d];
    sh[d] = nv;
    __syncthreads();
    const int dm = d & 63;
    float f = 1.f / powf(10000.f, (float)(2 * dm) * (1.f / DH));
    float cs, sn; sincosf((float)s * f, &sn, &cs);
    float rot = (d < 64) ? -sh[d + 64] : sh[d - 64];
    float qs = (nv * cs + rot * sn) * 0.08838834764831845f;

    __half* row = g_qa + ((size_t)h * SDIM + s) * KQ;
    uint32_t H, L; fold2h(qs, H, L);
    row[d]       = __ushort_as_half((unsigned short)H);
    row[128 + d] = __ushort_as_half((unsigned short)L);
    if (d < 32) {
        float bv = 0.f;
        if (h < NHG) bv = gscale[h] * (h < NSYM ? 0.5f : 1.f)
                         * g_pr[(size_t)s * NOUT + CRQ + h * RDIM + d];
        row[256 + d] = __float2half_rn(bv);
    } else if (d < 64) {
        int r = d - 32;
        float bv = 0.f;
        if (h < NSYM) bv = gscale[h] * 0.5f * g_pr[(size_t)s * NOUT + CRK + h * RDIM + r];
        row[288 + r] = __float2half_rn(bv);
    }
}

// ---------------- fused RMSNorm + RoPE + fold into kb (fp16) ----------------
__global__ __launch_bounds__(128) void norm_fill_kb(const float* __restrict__ w)
{
    const int s = blockIdx.x, kvh = blockIdx.y, d = threadIdx.x;
    float v = g_pr[(size_t)s * NOUT + CK + kvh * DH + d];
    float ss = v * v;
#pragma unroll
    for (int o = 16; o; o >>= 1) ss += __shfl_xor_sync(0xffffffffu, ss, o);
    __shared__ float r4[4];
    __shared__ float sh[DH];
    if ((d & 31) == 0) r4[d >> 5] = ss;
    __syncthreads();
    float nv = v * rsqrtf((r4[0]+r4[1]+r4[2]+r4[3]) * (1.f / DH) + 1e-6f) * w[d];
    sh[d] = nv;
    __syncthreads();
    const int dm = d & 63;
    float f = 1.f / powf(10000.f, (float)(2 * dm) * (1.f / DH));
    float cs, sn; sincosf((float)s * f, &sn, &cs);
    float rot = (d < 64) ? -sh[d + 64] : sh[d - 64];
    float kf = nv * cs + rot * sn;
    __half kh = __float2half_rn(kf);

#pragma unroll
    for (int e = 0; e < 4; e++) {
        int h = kvh * 4 + e;
        __half* row = g_kb + ((size_t)h * SDIM + s) * KQ;
        row[d]       = kh;
        row[128 + d] = kh;
        if (d < 32) {
            float bv = (h < NHG) ? g_pr[(size_t)s * NOUT + CRK + h * RDIM + d] : 0.f;
            row[256 + d] = __float2half_rn(bv);
        } else if (d < 64) {
            int r = d - 32;
            float bv = (h < NSYM) ? g_pr[(size_t)s * NOUT + CRQ + h * RDIM + r] : 0.f;
            row[288 + r] = __float2half_rn(bv);
        }
    }
}

// ---------------- fill vth (smem transpose, fp16 single) ----------------
__global__ __launch_bounds__(128) void fill_vh()
{
    __shared__ float sm[64][129];
    const int jb = blockIdx.x, kvh = blockIdx.y;
    const int tid = threadIdx.x;
    for (int jj = 0; jj < 64; jj++)
        sm[jj][tid] = g_pr[(size_t)(jb * 64 + jj) * NOUT + CV + kvh * DH + tid];
    __syncthreads();
    const int w = tid >> 5, ln = tid & 31;
    for (int d = w; d < DH; d += 4) {
        __half h0 = __float2half_rn(sm[2*ln][d]);
        __half h1 = __float2half_rn(sm[2*ln+1][d]);
        uint32_t* oh = (uint32_t*)(g_vth + (size_t)(kvh * DH + d) * SDIM + jb * 64);
        oh[ln] = (uint32_t)__half_as_ushort(h0) | ((uint32_t)__half_as_ushort(h1) << 16);
    }
}

// ---------------- Host ----------------
extern "C" void kernel_launch(void* const* d_in, const int* in_sizes, int n_in,
                              void* d_out, int out_size)
{
    const float* x   = (const float*)d_in[0];
    const float* Wq  = (const float*)d_in[1];
    const float* Wk  = (const float*)d_in[2];
    const float* Wv  = (const float*)d_in[3];
    const float* Wo  = (const float*)d_in[4];
    const float* qnw = (const float*)d_in[5];
    const float* knw = (const float*)d_in[6];
    const float* Wrq = (const float*)d_in[7];
    const float* Wrk = (const float*)d_in[8];
    const float* gsc = (const float*)d_in[9];
    float* out = (float*)d_out;

    float *pr, *rs;
    __half *xh, *xl, *wh, *woh, *aoh, *aol;
    cudaGetSymbolAddress((void**)&pr,  g_pr);
    cudaGetSymbolAddress((void**)&rs,  g_rs);
    cudaGetSymbolAddress((void**)&xh,  g_xh);
    cudaGetSymbolAddress((void**)&xl,  g_xl);
    cudaGetSymbolAddress((void**)&wh,  g_wh);
    cudaGetSymbolAddress((void**)&woh, g_woh);
    cudaGetSymbolAddress((void**)&aoh, g_aoh);
    cudaGetSymbolAddress((void**)&aol, g_aol);

    cudaFuncSetAttribute(gemm2,      cudaFuncAttributeMaxDynamicSharedMemorySize, 65536);
    cudaFuncSetAttribute(scores_mma, cudaFuncAttributeMaxDynamicSharedMemorySize, 98304);
    cudaFuncSetAttribute(av_mma,     cudaFuncAttributeMaxDynamicSharedMemorySize, 65536);

    split_x<<<8192, 256>>>(x, xh, xl, SDIM*EDIM/2);
    split_w1<<<12288, 256>>>(Wq, Wk, Wv);
    split_w2<<<11264, 256>>>(Wrq, Wrk, Wo);

    // index 3 under ncu: merged projection GEMM (fp16, shared-B inner)
    gemm2<<<dim3(NOUT/128, SDIM/64), 256, 65536>>>(xh, xl, wh, pr, NOUT, EDIM);

    cudaMemsetAsync(rs, 0, NH * SDIM * sizeof(float));

    norm_fill_qa<<<dim3(SDIM, NH),  128>>>(qnw, gsc);
    norm_fill_kb<<<dim3(SDIM, NKV), 128>>>(knw);
    fill_vh<<<dim3(SDIM/64, NKV), 128>>>();

    scores_mma<<<dim3(136, NH), 256, 98304>>>();
    av_mma<<<dim3(16, NH), 256, 65536>>>();

    gemm2<<<dim3(EDIM/128, SDIM/64), 256, 65536>>>(aoh, aol, woh, out, EDIM, EDIM);
}

// round 13
// speedup vs baseline: 1.9377x; 1.1162x over previous
#include <cuda_runtime.h>
#include <cuda_fp16.h>
#include <math.h>
#include <stdint.h>

#define SDIM 2048
#define EDIM 2048
#define NH   16
#define NKV  4
#define DH   128
#define NHG  12
#define RDIM 32
#define NSYM 4
#define NOUT 3840
#define CQ   0
#define CK   2048
#define CV   2560
#define CRQ  3072
#define CRK  3456
#define KQ   192

static __device__ float g_pr[SDIM*NOUT];
static __device__ float g_rs[NH*SDIM];                      // row sums of scaled exp
static __device__ __half g_eh [(size_t)NH*SDIM*SDIM];       // exp(scores)/16, masked=0
static __device__ __half g_xh [SDIM*EDIM];
static __device__ __half g_xl [SDIM*EDIM];
static __device__ __half g_wh [(size_t)NOUT*EDIM];
static __device__ __half g_woh[(size_t)EDIM*EDIM];
static __device__ __half g_aoh[(size_t)SDIM*EDIM];
static __device__ __half g_aol[(size_t)SDIM*EDIM];
static __device__ __half g_qa [(size_t)NH*SDIM*KQ];
static __device__ __half g_kb [(size_t)NH*SDIM*KQ];
static __device__ __half g_vth[(size_t)NKV*DH*SDIM];

// ---------------- PTX helpers ----------------
__device__ __forceinline__ uint32_t smem_u32(const void* p) {
    uint32_t a;
    asm("{ .reg .u64 t; cvta.to.shared.u64 t, %1; cvt.u32.u64 %0, t; }" : "=r"(a) : "l"(p));
    return a;
}
__device__ __forceinline__ void cpa16(uint32_t d, const void* g) {
    asm volatile("cp.async.cg.shared.global [%0], [%1], 16;" :: "r"(d), "l"(g));
}
__device__ __forceinline__ void cp_commit() { asm volatile("cp.async.commit_group;" ::: "memory"); }
template<int N> __device__ __forceinline__ void cp_wait() {
    asm volatile("cp.async.wait_group %0;" :: "n"(N) : "memory");
}
__device__ __forceinline__ void ldm_x4(uint32_t& r0, uint32_t& r1, uint32_t& r2, uint32_t& r3,
                                       uint32_t addr) {
    asm volatile("ldmatrix.sync.aligned.m8n8.x4.shared.b16 {%0,%1,%2,%3}, [%4];"
                 : "=r"(r0), "=r"(r1), "=r"(r2), "=r"(r3) : "r"(addr));
}
__device__ __forceinline__ void mma_f16(float* d, const uint32_t* a, const uint32_t* b) {
    asm volatile("mma.sync.aligned.m16n8k16.row.col.f32.f16.f16.f32 "
                 "{%0,%1,%2,%3}, {%4,%5,%6,%7}, {%8,%9}, {%0,%1,%2,%3};"
                 : "+f"(d[0]), "+f"(d[1]), "+f"(d[2]), "+f"(d[3])
                 : "r"(a[0]), "r"(a[1]), "r"(a[2]), "r"(a[3]), "r"(b[0]), "r"(b[1]));
}
__device__ __forceinline__ void fold2h(float v, uint32_t& H, uint32_t& L) {
    __half h = __float2half_rn(v);
    __half l = __float2half_rn(v - __half2float(h));
    H = __half_as_ushort(h); L = __half_as_ushort(l);
}
__device__ __forceinline__ void sbody2(const float* s, __half* dh, __half* dl, int i) {
    float2 v = ((const float2*)s)[i];
    uint32_t H0, L0, H1, L1;
    fold2h(v.x, H0, L0); fold2h(v.y, H1, L1);
    ((uint32_t*)dh)[i] = H0 | (H1 << 16);
    ((uint32_t*)dl)[i] = L0 | (L1 << 16);
}
__device__ __forceinline__ void sbody1(const float* s, __half* dh, int i) {
    float2 v = ((const float2*)s)[i];
    __half h0 = __float2half_rn(v.x), h1 = __float2half_rn(v.y);
    ((uint32_t*)dh)[i] = (uint32_t)__half_as_ushort(h0)
                       | ((uint32_t)__half_as_ushort(h1) << 16);
}

__global__ __launch_bounds__(256) void split_x(
    const float* __restrict__ s, __half* __restrict__ dh,
    __half* __restrict__ dl, int npairs)
{
    int i = blockIdx.x * 256 + threadIdx.x;
    if (i < npairs) sbody2(s, dh, dl, i);
}
__global__ __launch_bounds__(256) void split_w1(
    const float* __restrict__ wq, const float* __restrict__ wk,
    const float* __restrict__ wv)
{
    int i = blockIdx.x * 256 + threadIdx.x;
    const int A = 2097152, B = 2621440, C = 3145728;
    if      (i < A) sbody1(wq, g_wh + (size_t)CQ * EDIM, i);
    else if (i < B) sbody1(wk, g_wh + (size_t)CK * EDIM, i - A);
    else if (i < C) sbody1(wv, g_wh + (size_t)CV * EDIM, i - B);
}
__global__ __launch_bounds__(256) void split_w2(
    const float* __restrict__ wrq, const float* __restrict__ wrk,
    const float* __restrict__ wo)
{
    int i = blockIdx.x * 256 + threadIdx.x;
    const int A = 393216, B = 786432, C = 2883584;
    if      (i < A) sbody1(wrq, g_wh + (size_t)CRQ * EDIM, i);
    else if (i < B) sbody1(wrk, g_wh + (size_t)CRK * EDIM, i - A);
    else if (i < C) sbody1(wo,  g_woh, i - B);
}

// ---------------- shared machinery ----------------
#define GEMM_PREAMBLE                                                           \
    extern __shared__ __align__(1024) char dsm[];                               \
    const uint32_t sb = smem_u32(dsm);                                          \
    const int tid = threadIdx.x;                                                \
    const int l = tid & 31, wid = tid >> 5;                                     \
    const int cch = tid & 7;                                                    \
    const int akh = (l >> 4);                                                   \
    const int bkh = (l >> 3) & 1;                                               \
    const int lsw = l & 7;

#define LOAD128(base, P, ld, step) do {                                         \
    const __half* G = (P) + (size_t)(step) * 64;                                \
    _Pragma("unroll")                                                           \
    for (int it = 0; it < 4; it++) {                                            \
        int row = (tid >> 3) + 32 * it;                                         \
        uint32_t sw = row * 128u + 16u * (cch ^ (row & 7));                     \
        cpa16((base) + sw, G + (size_t)row * (ld) + cch * 8);                   \
    } } while (0)

#define LOAD64(base, P, ld, step) do {                                          \
    const __half* G = (P) + (size_t)(step) * 64;                                \
    _Pragma("unroll")                                                           \
    for (int it = 0; it < 2; it++) {                                            \
        int row = (tid >> 3) + 32 * it;                                         \
        uint32_t sw = row * 128u + 16u * (cch ^ (row & 7));                     \
        cpa16((base) + sw, G + (size_t)row * (ld) + cch * 8);                   \
    } } while (0)

#define INNER_128(Ab, Bb)                                                       \
    _Pragma("unroll")                                                           \
    for (int kk = 0; kk < 4; kk++) {                                            \
        uint32_t af[4][4], bf[4][2];                                            \
        _Pragma("unroll")                                                       \
        for (int tm = 0; tm < 4; tm++)                                          \
            ldm_x4(af[tm][0], af[tm][1], af[tm][2], af[tm][3],                  \
                   (Ab) + (uint32_t)(ar + tm * 16) * 128u + 16u * (((kk << 1) + akh) ^ lsw)); \
        _Pragma("unroll")                                                       \
        for (int np = 0; np < 2; np++) {                                        \
            uint32_t r0, r1, r2, r3;                                            \
            ldm_x4(r0, r1, r2, r3,                                              \
                   (Bb) + (uint32_t)(br + np * 16) * 128u + 16u * (((kk << 1) + bkh) ^ lsw)); \
            bf[2*np][0] = r0; bf[2*np][1] = r1; bf[2*np+1][0] = r2; bf[2*np+1][1] = r3; \
        }                                                                       \
        _Pragma("unroll")                                                       \
        for (int tm = 0; tm < 4; tm++)                                          \
            _Pragma("unroll")                                                   \
            for (int tn = 0; tn < 4; tn++) mma_f16(acc[tm][tn], af[tm], bf[tn]); \
    }

// ---------------- 2-product fp16 GEMM (proj / Wo): shared-B inner ----------
__global__ __launch_bounds__(256, 3) void gemm2(
    const __half* __restrict__ Ah, const __half* __restrict__ Al,
    const __half* __restrict__ Bh,
    float* __restrict__ C, int ldc, int K)
{
    GEMM_PREAMBLE
    const int wm = wid & 1, wn = wid >> 1;
    const int m0 = blockIdx.y << 6, n0 = blockIdx.x << 7;
    const int steps = K >> 6;
    const __half* Ah_ = Ah + (size_t)m0 * K;
    const __half* Al_ = Al + (size_t)m0 * K;
    const __half* Bh_ = Bh + (size_t)n0 * K;

    float acc[2][4][4];
#pragma unroll
    for (int i = 0; i < 2; i++)
#pragma unroll
        for (int j = 0; j < 4; j++)
#pragma unroll
            for (int r = 0; r < 4; r++) acc[i][j][r] = 0.f;

    const int ar = wm * 32 + (l & 7) + (l & 8);
    const int br = wn * 32 + (l & 7) + 8 * (l >> 4);

    LOAD64(sb, Ah_, K, 0); LOAD64(sb + 8192u, Al_, K, 0);
    LOAD128(sb + 16384u, Bh_, K, 0); cp_commit();

    for (int s = 0; s < steps; s++) {
        cp_wait<0>();
        __syncthreads();
        if (s + 1 < steps) {
            uint32_t b2 = sb + ((s + 1) & 1) * 32768u;
            LOAD64(b2, Ah_, K, s + 1); LOAD64(b2 + 8192u, Al_, K, s + 1);
            LOAD128(b2 + 16384u, Bh_, K, s + 1); cp_commit();
        }
        const uint32_t Ast = sb + (s & 1) * 32768u;
        const uint32_t Bst = Ast + 16384u;
#pragma unroll
        for (int kk = 0; kk < 4; kk++) {
            uint32_t bf[4][2], afh[2][4], afl[2][4];
#pragma unroll
            for (int np = 0; np < 2; np++) {
                uint32_t r0, r1, r2, r3;
                ldm_x4(r0, r1, r2, r3,
                       Bst + (uint32_t)(br + np * 16) * 128u + 16u * (((kk << 1) + bkh) ^ lsw));
                bf[2*np][0] = r0; bf[2*np][1] = r1; bf[2*np+1][0] = r2; bf[2*np+1][1] = r3;
            }
#pragma unroll
            for (int tm = 0; tm < 2; tm++) {
                ldm_x4(afh[tm][0], afh[tm][1], afh[tm][2], afh[tm][3],
                       Ast + (uint32_t)(ar + tm * 16) * 128u + 16u * (((kk << 1) + akh) ^ lsw));
                ldm_x4(afl[tm][0], afl[tm][1], afl[tm][2], afl[tm][3],
                       Ast + 8192u + (uint32_t)(ar + tm * 16) * 128u + 16u * (((kk << 1) + akh) ^ lsw));
            }
#pragma unroll
            for (int tm = 0; tm < 2; tm++)
#pragma unroll
                for (int tn = 0; tn < 4; tn++) mma_f16(acc[tm][tn], afh[tm], bf[tn]);
#pragma unroll
            for (int tm = 0; tm < 2; tm++)
#pragma unroll
                for (int tn = 0; tn < 4; tn++) mma_f16(acc[tm][tn], afl[tm], bf[tn]);
        }
    }
    const int er = m0 + wm * 32 + (l >> 2);
    const int ec = n0 + wn * 32 + 2 * (l & 3);
#pragma unroll
    for (int tm = 0; tm < 2; tm++)
#pragma unroll
        for (int tn = 0; tn < 4; tn++) {
            float* p0 = C + (size_t)(er + tm * 16) * ldc + ec + tn * 8;
            float* p1 = C + (size_t)(er + tm * 16 + 8) * ldc + ec + tn * 8;
            *(float2*)p0 = make_float2(acc[tm][tn][0], acc[tm][tn][1]);
            *(float2*)p1 = make_float2(acc[tm][tn][2], acc[tm][tn][3]);
        }
}

// ---------------- scores: mma (KQ=192) + exp/16 -> fp16 + row-sum atomics ---
__global__ __launch_bounds__(256) void scores_mma()
{
    GEMM_PREAMBLE
    const int wm = wid & 1, wn = wid >> 1;
    const int h = blockIdx.y, idx = blockIdx.x;
    int ti = (int)((sqrtf(8.f * idx + 1.f) - 1.f) * 0.5f);
    while ((ti + 1) * (ti + 2) / 2 <= idx) ti++;
    while (ti * (ti + 1) / 2 > idx) ti--;
    const int tj = idx - ti * (ti + 1) / 2;
    const int i0 = ti << 7, j0 = tj << 7;
    const __half* Ab_ = g_qa + ((size_t)h * SDIM + i0) * KQ;
    const __half* Bb_ = g_kb + ((size_t)h * SDIM + j0) * KQ;
    const int steps = KQ >> 6;   // 3

    float acc[4][4][4];
#pragma unroll
    for (int i = 0; i < 4; i++)
#pragma unroll
        for (int j = 0; j < 4; j++)
#pragma unroll
            for (int r = 0; r < 4; r++) acc[i][j][r] = 0.f;
    const int ar = wm * 64 + (l & 7) + (l & 8);
    const int br = wn * 32 + (l & 7) + 8 * (l >> 4);

    LOAD128(sb, Ab_, KQ, 0); LOAD128(sb + 16384u, Bb_, KQ, 0); cp_commit();
    LOAD128(sb + 32768u, Ab_, KQ, 1); LOAD128(sb + 49152u, Bb_, KQ, 1); cp_commit();

    for (int s = 0; s < steps; s++) {
        cp_wait<1>();
        __syncthreads();
        if (s + 2 < steps) {
            uint32_t b2 = sb + ((s + 2) % 3) * 32768u;
            LOAD128(b2, Ab_, KQ, s + 2); LOAD128(b2 + 16384u, Bb_, KQ, s + 2);
        }
        cp_commit();
        const uint32_t Ab = sb + (s % 3) * 32768u;
        const uint32_t Bb = Ab + 16384u;
        INNER_128(Ab, Bb)
    }
    // epilogue: e = exp(masked s)/16 -> fp16, accumulate row sums (scaled)
    const int er = i0 + wm * 64 + (l >> 2);
    const int ec = j0 + wn * 32 + 2 * (l & 3);
    float rsum[4][2];
#pragma unroll
    for (int tm = 0; tm < 4; tm++) { rsum[tm][0] = 0.f; rsum[tm][1] = 0.f; }
#pragma unroll
    for (int tm = 0; tm < 4; tm++)
#pragma unroll
        for (int tn = 0; tn < 4; tn++) {
            int r0 = er + tm * 16, r1 = r0 + 8, c = ec + tn * 8;
            float e00 = (c     <= r0) ? __expf(acc[tm][tn][0]) * 0.0625f : 0.f;
            float e01 = (c + 1 <= r0) ? __expf(acc[tm][tn][1]) * 0.0625f : 0.f;
            float e10 = (c     <= r1) ? __expf(acc[tm][tn][2]) * 0.0625f : 0.f;
            float e11 = (c + 1 <= r1) ? __expf(acc[tm][tn][3]) * 0.0625f : 0.f;
            __half2 v0; v0.x = __float2half_rn(e00); v0.y = __float2half_rn(e01);
            __half2 v1; v1.x = __float2half_rn(e10); v1.y = __float2half_rn(e11);
            *(__half2*)(g_eh + ((size_t)h * SDIM + r0) * SDIM + c) = v0;
            *(__half2*)(g_eh + ((size_t)h * SDIM + r1) * SDIM + c) = v1;
            rsum[tm][0] += e00 + e01;
            rsum[tm][1] += e10 + e11;
        }
#pragma unroll
    for (int tm = 0; tm < 4; tm++)
#pragma unroll
        for (int rr = 0; rr < 2; rr++) {
            float v = rsum[tm][rr];
            v += __shfl_xor_sync(0xffffffffu, v, 1);
            v += __shfl_xor_sync(0xffffffffu, v, 2);
            if ((l & 3) == 0)
                atomicAdd(&g_rs[h * SDIM + er + tm * 16 + rr * 8], v);
        }
}

// ---------------- AV: pure single-product GEMM over eh, normalize at end ----
// smem/stage: A(eh) 8KB @0, B(vth) 16KB @8192; 2 stages, stride 24576 (48KB).
__global__ __launch_bounds__(256) void av_mma()
{
    GEMM_PREAMBLE
    const int wm = wid & 1, wn = wid >> 1;
    const int h = blockIdx.y;
    const __half* Vh_ = g_vth + (size_t)(h >> 2) * DH * SDIM;

    const int ar = wm * 32 + (l & 7) + (l & 8);
    const int br = wn * 32 + (l & 7) + 8 * (l >> 4);

    for (int half = 0; half < 2; half++) {
        const int mt = half ? 31 - (int)blockIdx.x : (int)blockIdx.x;
        const int m0 = mt << 6;
        const int steps = mt + 1;
        const __half* Ae_ = g_eh + ((size_t)h * SDIM + m0) * SDIM;

        float acc[2][4][4];
#pragma unroll
        for (int i = 0; i < 2; i++)
#pragma unroll
            for (int j = 0; j < 4; j++)
#pragma unroll
                for (int r = 0; r < 4; r++) acc[i][j][r] = 0.f;

        LOAD64(sb, Ae_, SDIM, 0);
        LOAD128(sb + 8192u, Vh_, SDIM, 0);
        cp_commit();

        for (int s = 0; s < steps; s++) {
            cp_wait<0>();
            __syncthreads();
            if (s + 1 < steps) {
                uint32_t b2 = sb + ((s + 1) & 1) * 24576u;
                LOAD64(b2, Ae_, SDIM, s + 1);
                LOAD128(b2 + 8192u, Vh_, SDIM, s + 1);
                cp_commit();
            }
            const uint32_t Ast = sb + (s & 1) * 24576u;
            const uint32_t Bst = Ast + 8192u;
#pragma unroll
            for (int kk = 0; kk < 4; kk++) {
                uint32_t bf[4][2], af[2][4];
#pragma unroll
                for (int np = 0; np < 2; np++) {
                    uint32_t r0, r1, r2, r3;
                    ldm_x4(r0, r1, r2, r3,
                           Bst + (uint32_t)(br + np * 16) * 128u + 16u * (((kk << 1) + bkh) ^ lsw));
                    bf[2*np][0] = r0; bf[2*np][1] = r1; bf[2*np+1][0] = r2; bf[2*np+1][1] = r3;
                }
#pragma unroll
                for (int tm = 0; tm < 2; tm++)
                    ldm_x4(af[tm][0], af[tm][1], af[tm][2], af[tm][3],
                           Ast + (uint32_t)(ar + tm * 16) * 128u + 16u * (((kk << 1) + akh) ^ lsw));
#pragma unroll
                for (int tm = 0; tm < 2; tm++)
#pragma unroll
                    for (int tn = 0; tn < 4; tn++) mma_f16(acc[tm][tn], af[tm], bf[tn]);
            }
        }
        // epilogue: normalize by rowsum (same scaling -> exact) and fold
        const int er = m0 + wm * 32 + (l >> 2);
        const int ecl = wn * 32 + 2 * (l & 3);
#pragma unroll
        for (int tm = 0; tm < 2; tm++) {
            float ir0 = 1.f / g_rs[h * SDIM + er + tm * 16];
            float ir1 = 1.f / g_rs[h * SDIM + er + tm * 16 + 8];
#pragma unroll
            for (int tn = 0; tn < 4; tn++) {
                int c = h * DH + ecl + tn * 8;
                int r0 = er + tm * 16, r1 = r0 + 8;
                float v00 = acc[tm][tn][0] * ir0, v01 = acc[tm][tn][1] * ir0;
                float v10 = acc[tm][tn][2] * ir1, v11 = acc[tm][tn][3] * ir1;
                uint32_t H0, L0, H1, L1;
                fold2h(v00, H0, L0); fold2h(v01, H1, L1);
                ((uint32_t*)g_aoh)[(size_t)r0 * (EDIM/2) + (c >> 1)] = H0 | (H1 << 16);
                ((uint32_t*)g_aol)[(size_t)r0 * (EDIM/2) + (c >> 1)] = L0 | (L1 << 16);
                fold2h(v10, H0, L0); fold2h(v11, H1, L1);
                ((uint32_t*)g_aoh)[(size_t)r1 * (EDIM/2) + (c >> 1)] = H0 | (H1 << 16);
                ((uint32_t*)g_aol)[(size_t)r1 * (EDIM/2) + (c >> 1)] = L0 | (L1 << 16);
            }
        }
        __syncthreads();
    }
}

// ---------------- fused RMSNorm + RoPE + fill qa (qh + bias) ----------------
__global__ __launch_bounds__(128) void norm_fill_qa(
    const float* __restrict__ w, const float* __restrict__ gscale)
{
    const int s = blockIdx.x, h = blockIdx.y, d = threadIdx.x;
    float v = g_pr[(size_t)s * NOUT + CQ + h * DH + d];
    float ss = v * v;
#pragma unroll
    for (int o = 16; o; o >>= 1) ss += __shfl_xor_sync(0xffffffffu, ss, o);
    __shared__ float r4[4];
    __shared__ float sh[DH];
    if ((d & 31) == 0) r4[d >> 5] = ss;
    __syncthreads();
    float nv = v * rsqrtf((r4[0]+r4[1]+r4[2]+r4[3]) * (1.f / DH) + 1e-6f) * w[d];
    sh[d] = nv;
    __syncthreads();
    const int dm = d & 63;
    float f = 1.f / powf(10000.f, (float)(2 * dm) * (1.f / DH));
    float cs, sn; sincosf((float)s * f, &sn, &cs);
    float rot = (d < 64) ? -sh[d + 64] : sh[d - 64];
    float qs = (nv * cs + rot * sn) * 0.08838834764831845f;

    __half* row = g_qa + ((size_t)h * SDIM + s) * KQ;
    row[d] = __float2half_rn(qs);
    if (d < 32) {
        float bv = 0.f;
        if (h < NHG) bv = gscale[h] * (h < NSYM ? 0.5f : 1.f)
                         * g_pr[(size_t)s * NOUT + CRQ + h * RDIM + d];
        row[128 + d] = __float2half_rn(bv);
    } else if (d < 64) {
        int r = d - 32;
        float bv = 0.f;
        if (h < NSYM) bv = gscale[h] * 0.5f * g_pr[(size_t)s * NOUT + CRK + h * RDIM + r];
        row[160 + r] = __float2half_rn(bv);
    }
}

// ---------------- fused RMSNorm + RoPE + fill kb (kh + bias) ----------------
__global__ __launch_bounds__(128) void norm_fill_kb(const float* __restrict__ w)
{
    const int s = blockIdx.x, kvh = blockIdx.y, d = threadIdx.x;
    float v = g_pr[(size_t)s * NOUT + CK + kvh * DH + d];
    float ss = v * v;
#pragma unroll
    for (int o = 16; o; o >>= 1) ss += __shfl_xor_sync(0xffffffffu, ss, o);
    __shared__ float r4[4];
    __shared__ float sh[DH];
    if ((d & 31) == 0) r4[d >> 5] = ss;
    __syncthreads();
    float nv = v * rsqrtf((r4[0]+r4[1]+r4[2]+r4[3]) * (1.f / DH) + 1e-6f) * w[d];
    sh[d] = nv;
    __syncthreads();
    const int dm = d & 63;
    float f = 1.f / powf(10000.f, (float)(2 * dm) * (1.f / DH));
    float cs, sn; sincosf((float)s * f, &sn, &cs);
    float rot = (d < 64) ? -sh[d + 64] : sh[d - 64];
    __half kh = __float2half_rn(nv * cs + rot * sn);

#pragma unroll
    for (int e = 0; e < 4; e++) {
        int h = kvh * 4 + e;
        __half* row = g_kb + ((size_t)h * SDIM + s) * KQ;
        row[d] = kh;
        if (d < 32) {
            float bv = (h < NHG) ? g_pr[(size_t)s * NOUT + CRK + h * RDIM + d] : 0.f;
            row[128 + d] = __float2half_rn(bv);
        } else if (d < 64) {
            int r = d - 32;
            float bv = (h < NSYM) ? g_pr[(size_t)s * NOUT + CRQ + h * RDIM + r] : 0.f;
            row[160 + r] = __float2half_rn(bv);
        }
    }
}

// ---------------- fill vth (smem transpose, fp16 single) ----------------
__global__ __launch_bounds__(128) void fill_vh()
{
    __shared__ float sm[64][129];
    const int jb = blockIdx.x, kvh = blockIdx.y;
    const int tid = threadIdx.x;
    for (int jj = 0; jj < 64; jj++)
        sm[jj][tid] = g_pr[(size_t)(jb * 64 + jj) * NOUT + CV + kvh * DH + tid];
    __syncthreads();
    const int w = tid >> 5, ln = tid & 31;
    for (int d = w; d < DH; d += 4) {
        __half h0 = __float2half_rn(sm[2*ln][d]);
        __half h1 = __float2half_rn(sm[2*ln+1][d]);
        uint32_t* oh = (uint32_t*)(g_vth + (size_t)(kvh * DH + d) * SDIM + jb * 64);
        oh[ln] = (uint32_t)__half_as_ushort(h0) | ((uint32_t)__half_as_ushort(h1) << 16);
    }
}

// ---------------- Host ----------------
extern "C" void kernel_launch(void* const* d_in, const int* in_sizes, int n_in,
                              void* d_out, int out_size)
{
    const float* x   = (const float*)d_in[0];
    const float* Wq  = (const float*)d_in[1];
    const float* Wk  = (const float*)d_in[2];
    const float* Wv  = (const float*)d_in[3];
    const float* Wo  = (const float*)d_in[4];
    const float* qnw = (const float*)d_in[5];
    const float* knw = (const float*)d_in[6];
    const float* Wrq = (const float*)d_in[7];
    const float* Wrk = (const float*)d_in[8];
    const float* gsc = (const float*)d_in[9];
    float* out = (float*)d_out;

    float *pr, *rs;
    __half *xh, *xl, *wh, *woh, *aoh, *aol;
    cudaGetSymbolAddress((void**)&pr,  g_pr);
    cudaGetSymbolAddress((void**)&rs,  g_rs);
    cudaGetSymbolAddress((void**)&xh,  g_xh);
    cudaGetSymbolAddress((void**)&xl,  g_xl);
    cudaGetSymbolAddress((void**)&wh,  g_wh);
    cudaGetSymbolAddress((void**)&woh, g_woh);
    cudaGetSymbolAddress((void**)&aoh, g_aoh);
    cudaGetSymbolAddress((void**)&aol, g_aol);

    cudaFuncSetAttribute(gemm2,      cudaFuncAttributeMaxDynamicSharedMemorySize, 65536);
    cudaFuncSetAttribute(scores_mma, cudaFuncAttributeMaxDynamicSharedMemorySize, 98304);
    cudaFuncSetAttribute(av_mma,     cudaFuncAttributeMaxDynamicSharedMemorySize, 49152);

    split_x<<<8192, 256>>>(x, xh, xl, SDIM*EDIM/2);
    split_w1<<<12288, 256>>>(Wq, Wk, Wv);
    split_w2<<<11264, 256>>>(Wrq, Wrk, Wo);

    // index 3 under ncu: merged projection GEMM
    gemm2<<<dim3(NOUT/128, SDIM/64), 256, 65536>>>(xh, xl, wh, pr, NOUT, EDIM);

    cudaMemsetAsync(rs, 0, NH * SDIM * sizeof(float));

    norm_fill_qa<<<dim3(SDIM, NH),  128>>>(qnw, gsc);
    norm_fill_kb<<<dim3(SDIM, NKV), 128>>>(knw);
    fill_vh<<<dim3(SDIM/64, NKV), 128>>>();

    scores_mma<<<dim3(136, NH), 256, 98304>>>();
    av_mma<<<dim3(16, NH), 256, 49152>>>();

    gemm2<<<dim3(EDIM/128, SDIM/64), 256, 65536>>>(aoh, aol, woh, out, EDIM, EDIM);
}

// round 14
// speedup vs baseline: 2.5396x; 1.3106x over previous
#include <cuda_runtime.h>
#include <cuda_fp16.h>
#include <math.h>
#include <stdint.h>

#define SDIM 2048
#define EDIM 2048
#define NH   16
#define NKV  4
#define DH   128
#define NHG  12
#define RDIM 32
#define NSYM 4
#define NOUT 3840
#define CQ   0
#define CK   2048
#define CV   2560
#define CRQ  3072
#define CRK  3456
#define KQ   192

static __device__ float g_pr[SDIM*NOUT];
static __device__ float g_rs[NH*SDIM];                      // row sums of scaled exp
static __device__ __half g_eh [(size_t)NH*SDIM*SDIM];       // exp(scores)/16, masked=0
static __device__ __half g_xh [SDIM*EDIM];
static __device__ __half g_wh [(size_t)NOUT*EDIM];
static __device__ __half g_woh[(size_t)EDIM*EDIM];
static __device__ __half g_aoh[(size_t)SDIM*EDIM];
static __device__ __half g_qa [(size_t)NH*SDIM*KQ];
static __device__ __half g_kb [(size_t)NH*SDIM*KQ];
static __device__ __half g_vth[(size_t)NKV*DH*SDIM];

// ---------------- PTX helpers ----------------
__device__ __forceinline__ uint32_t smem_u32(const void* p) {
    uint32_t a;
    asm("{ .reg .u64 t; cvta.to.shared.u64 t, %1; cvt.u32.u64 %0, t; }" : "=r"(a) : "l"(p));
    return a;
}
__device__ __forceinline__ void cpa16(uint32_t d, const void* g) {
    asm volatile("cp.async.cg.shared.global [%0], [%1], 16;" :: "r"(d), "l"(g));
}
__device__ __forceinline__ void cp_commit() { asm volatile("cp.async.commit_group;" ::: "memory"); }
template<int N> __device__ __forceinline__ void cp_wait() {
    asm volatile("cp.async.wait_group %0;" :: "n"(N) : "memory");
}
__device__ __forceinline__ void ldm_x4(uint32_t& r0, uint32_t& r1, uint32_t& r2, uint32_t& r3,
                                       uint32_t addr) {
    asm volatile("ldmatrix.sync.aligned.m8n8.x4.shared.b16 {%0,%1,%2,%3}, [%4];"
                 : "=r"(r0), "=r"(r1), "=r"(r2), "=r"(r3) : "r"(addr));
}
__device__ __forceinline__ void mma_f16(float* d, const uint32_t* a, const uint32_t* b) {
    asm volatile("mma.sync.aligned.m16n8k16.row.col.f32.f16.f16.f32 "
                 "{%0,%1,%2,%3}, {%4,%5,%6,%7}, {%8,%9}, {%0,%1,%2,%3};"
                 : "+f"(d[0]), "+f"(d[1]), "+f"(d[2]), "+f"(d[3])
                 : "r"(a[0]), "r"(a[1]), "r"(a[2]), "r"(a[3]), "r"(b[0]), "r"(b[1]));
}
__device__ __forceinline__ void sbody1(const float* s, __half* dh, int i) {
    float2 v = ((const float2*)s)[i];
    __half h0 = __float2half_rn(v.x), h1 = __float2half_rn(v.y);
    ((uint32_t*)dh)[i] = (uint32_t)__half_as_ushort(h0)
                       | ((uint32_t)__half_as_ushort(h1) << 16);
}

__global__ __launch_bounds__(256) void split_x(
    const float* __restrict__ s, __half* __restrict__ dh, int npairs)
{
    int i = blockIdx.x * 256 + threadIdx.x;
    if (i < npairs) sbody1(s, dh, i);
}
__global__ __launch_bounds__(256) void split_w1(
    const float* __restrict__ wq, const float* __restrict__ wk,
    const float* __restrict__ wv)
{
    int i = blockIdx.x * 256 + threadIdx.x;
    const int A = 2097152, B = 2621440, C = 3145728;
    if      (i < A) sbody1(wq, g_wh + (size_t)CQ * EDIM, i);
    else if (i < B) sbody1(wk, g_wh + (size_t)CK * EDIM, i - A);
    else if (i < C) sbody1(wv, g_wh + (size_t)CV * EDIM, i - B);
}
__global__ __launch_bounds__(256) void split_w2(
    const float* __restrict__ wrq, const float* __restrict__ wrk,
    const float* __restrict__ wo)
{
    int i = blockIdx.x * 256 + threadIdx.x;
    const int A = 393216, B = 786432, C = 2883584;
    if      (i < A) sbody1(wrq, g_wh + (size_t)CRQ * EDIM, i);
    else if (i < B) sbody1(wrk, g_wh + (size_t)CRK * EDIM, i - A);
    else if (i < C) sbody1(wo,  g_woh, i - B);
}

// ---------------- shared machinery ----------------
#define GEMM_PREAMBLE                                                           \
    extern __shared__ __align__(1024) char dsm[];                               \
    const uint32_t sb = smem_u32(dsm);                                          \
    const int tid = threadIdx.x;                                                \
    const int l = tid & 31, wid = tid >> 5;                                     \
    const int cch = tid & 7;                                                    \
    const int akh = (l >> 4);                                                   \
    const int bkh = (l >> 3) & 1;                                               \
    const int lsw = l & 7;

#define LOAD128(base, P, ld, step) do {                                         \
    const __half* G = (P) + (size_t)(step) * 64;                                \
    _Pragma("unroll")                                                           \
    for (int it = 0; it < 4; it++) {                                            \
        int row = (tid >> 3) + 32 * it;                                         \
        uint32_t sw = row * 128u + 16u * (cch ^ (row & 7));                     \
        cpa16((base) + sw, G + (size_t)row * (ld) + cch * 8);                   \
    } } while (0)

#define LOAD64(base, P, ld, step) do {                                          \
    const __half* G = (P) + (size_t)(step) * 64;                                \
    _Pragma("unroll")                                                           \
    for (int it = 0; it < 2; it++) {                                            \
        int row = (tid >> 3) + 32 * it;                                         \
        uint32_t sw = row * 128u + 16u * (cch ^ (row & 7));                     \
        cpa16((base) + sw, G + (size_t)row * (ld) + cch * 8);                   \
    } } while (0)

#define INNER_128(Ab, Bb)                                                       \
    _Pragma("unroll")                                                           \
    for (int kk = 0; kk < 4; kk++) {                                            \
        uint32_t af[4][4], bf[4][2];                                            \
        _Pragma("unroll")                                                       \
        for (int tm = 0; tm < 4; tm++)                                          \
            ldm_x4(af[tm][0], af[tm][1], af[tm][2], af[tm][3],                  \
                   (Ab) + (uint32_t)(ar + tm * 16) * 128u + 16u * (((kk << 1) + akh) ^ lsw)); \
        _Pragma("unroll")                                                       \
        for (int np = 0; np < 2; np++) {                                        \
            uint32_t r0, r1, r2, r3;                                            \
            ldm_x4(r0, r1, r2, r3,                                              \
                   (Bb) + (uint32_t)(br + np * 16) * 128u + 16u * (((kk << 1) + bkh) ^ lsw)); \
            bf[2*np][0] = r0; bf[2*np][1] = r1; bf[2*np+1][0] = r2; bf[2*np+1][1] = r3; \
        }                                                                       \
        _Pragma("unroll")                                                       \
        for (int tm = 0; tm < 4; tm++)                                          \
            _Pragma("unroll")                                                   \
            for (int tn = 0; tn < 4; tn++) mma_f16(acc[tm][tn], af[tm], bf[tn]); \
    }

// ---------------- single-product fp16 GEMM (proj / Wo) ----------------
// CTA 64x128; stage: A 8KB @0, B 16KB @8192; 2 stages, stride 24576 (48KB).
__global__ __launch_bounds__(256, 3) void gemm1(
    const __half* __restrict__ Ah, const __half* __restrict__ Bh,
    float* __restrict__ C, int ldc, int K)
{
    GEMM_PREAMBLE
    const int wm = wid & 1, wn = wid >> 1;
    const int m0 = blockIdx.y << 6, n0 = blockIdx.x << 7;
    const int steps = K >> 6;
    const __half* Ah_ = Ah + (size_t)m0 * K;
    const __half* Bh_ = Bh + (size_t)n0 * K;

    float acc[2][4][4];
#pragma unroll
    for (int i = 0; i < 2; i++)
#pragma unroll
        for (int j = 0; j < 4; j++)
#pragma unroll
            for (int r = 0; r < 4; r++) acc[i][j][r] = 0.f;

    const int ar = wm * 32 + (l & 7) + (l & 8);
    const int br = wn * 32 + (l & 7) + 8 * (l >> 4);

    LOAD64(sb, Ah_, K, 0);
    LOAD128(sb + 8192u, Bh_, K, 0);
    cp_commit();

    for (int s = 0; s < steps; s++) {
        cp_wait<0>();
        __syncthreads();
        if (s + 1 < steps) {
            uint32_t b2 = sb + ((s + 1) & 1) * 24576u;
            LOAD64(b2, Ah_, K, s + 1);
            LOAD128(b2 + 8192u, Bh_, K, s + 1);
            cp_commit();
        }
        const uint32_t Ast = sb + (s & 1) * 24576u;
        const uint32_t Bst = Ast + 8192u;
#pragma unroll
        for (int kk = 0; kk < 4; kk++) {
            uint32_t bf[4][2], af[2][4];
#pragma unroll
            for (int np = 0; np < 2; np++) {
                uint32_t r0, r1, r2, r3;
                ldm_x4(r0, r1, r2, r3,
                       Bst + (uint32_t)(br + np * 16) * 128u + 16u * (((kk << 1) + bkh) ^ lsw));
                bf[2*np][0] = r0; bf[2*np][1] = r1; bf[2*np+1][0] = r2; bf[2*np+1][1] = r3;
            }
#pragma unroll
            for (int tm = 0; tm < 2; tm++)
                ldm_x4(af[tm][0], af[tm][1], af[tm][2], af[tm][3],
                       Ast + (uint32_t)(ar + tm * 16) * 128u + 16u * (((kk << 1) + akh) ^ lsw));
#pragma unroll
            for (int tm = 0; tm < 2; tm++)
#pragma unroll
                for (int tn = 0; tn < 4; tn++) mma_f16(acc[tm][tn], af[tm], bf[tn]);
        }
    }
    const int er = m0 + wm * 32 + (l >> 2);
    const int ec = n0 + wn * 32 + 2 * (l & 3);
#pragma unroll
    for (int tm = 0; tm < 2; tm++)
#pragma unroll
        for (int tn = 0; tn < 4; tn++) {
            float* p0 = C + (size_t)(er + tm * 16) * ldc + ec + tn * 8;
            float* p1 = C + (size_t)(er + tm * 16 + 8) * ldc + ec + tn * 8;
            *(float2*)p0 = make_float2(acc[tm][tn][0], acc[tm][tn][1]);
            *(float2*)p1 = make_float2(acc[tm][tn][2], acc[tm][tn][3]);
        }
}

// ---------------- scores: mma (KQ=192) + exp/16 -> fp16 + row-sum atomics ---
__global__ __launch_bounds__(256) void scores_mma()
{
    GEMM_PREAMBLE
    const int wm = wid & 1, wn = wid >> 1;
    const int h = blockIdx.y, idx = blockIdx.x;
    int ti = (int)((sqrtf(8.f * idx + 1.f) - 1.f) * 0.5f);
    while ((ti + 1) * (ti + 2) / 2 <= idx) ti++;
    while (ti * (ti + 1) / 2 > idx) ti--;
    const int tj = idx - ti * (ti + 1) / 2;
    const int i0 = ti << 7, j0 = tj << 7;
    const __half* Ab_ = g_qa + ((size_t)h * SDIM + i0) * KQ;
    const __half* Bb_ = g_kb + ((size_t)h * SDIM + j0) * KQ;
    const int steps = KQ >> 6;   // 3

    float acc[4][4][4];
#pragma unroll
    for (int i = 0; i < 4; i++)
#pragma unroll
        for (int j = 0; j < 4; j++)
#pragma unroll
            for (int r = 0; r < 4; r++) acc[i][j][r] = 0.f;
    const int ar = wm * 64 + (l & 7) + (l & 8);
    const int br = wn * 32 + (l & 7) + 8 * (l >> 4);

    LOAD128(sb, Ab_, KQ, 0); LOAD128(sb + 16384u, Bb_, KQ, 0); cp_commit();
    LOAD128(sb + 32768u, Ab_, KQ, 1); LOAD128(sb + 49152u, Bb_, KQ, 1); cp_commit();

    for (int s = 0; s < steps; s++) {
        cp_wait<1>();
        __syncthreads();
        if (s + 2 < steps) {
            uint32_t b2 = sb + ((s + 2) % 3) * 32768u;
            LOAD128(b2, Ab_, KQ, s + 2); LOAD128(b2 + 16384u, Bb_, KQ, s + 2);
        }
        cp_commit();
        const uint32_t Ab = sb + (s % 3) * 32768u;
        const uint32_t Bb = Ab + 16384u;
        INNER_128(Ab, Bb)
    }
    // epilogue: e = exp(masked s)/16 -> fp16, accumulate row sums (scaled)
    const int er = i0 + wm * 64 + (l >> 2);
    const int ec = j0 + wn * 32 + 2 * (l & 3);
    float rsum[4][2];
#pragma unroll
    for (int tm = 0; tm < 4; tm++) { rsum[tm][0] = 0.f; rsum[tm][1] = 0.f; }
#pragma unroll
    for (int tm = 0; tm < 4; tm++)
#pragma unroll
        for (int tn = 0; tn < 4; tn++) {
            int r0 = er + tm * 16, r1 = r0 + 8, c = ec + tn * 8;
            float e00 = (c     <= r0) ? __expf(acc[tm][tn][0]) * 0.0625f : 0.f;
            float e01 = (c + 1 <= r0) ? __expf(acc[tm][tn][1]) * 0.0625f : 0.f;
            float e10 = (c     <= r1) ? __expf(acc[tm][tn][2]) * 0.0625f : 0.f;
            float e11 = (c + 1 <= r1) ? __expf(acc[tm][tn][3]) * 0.0625f : 0.f;
            __half2 v0; v0.x = __float2half_rn(e00); v0.y = __float2half_rn(e01);
            __half2 v1; v1.x = __float2half_rn(e10); v1.y = __float2half_rn(e11);
            *(__half2*)(g_eh + ((size_t)h * SDIM + r0) * SDIM + c) = v0;
            *(__half2*)(g_eh + ((size_t)h * SDIM + r1) * SDIM + c) = v1;
            rsum[tm][0] += e00 + e01;
            rsum[tm][1] += e10 + e11;
        }
#pragma unroll
    for (int tm = 0; tm < 4; tm++)
#pragma unroll
        for (int rr = 0; rr < 2; rr++) {
            float v = rsum[tm][rr];
            v += __shfl_xor_sync(0xffffffffu, v, 1);
            v += __shfl_xor_sync(0xffffffffu, v, 2);
            if ((l & 3) == 0)
                atomicAdd(&g_rs[h * SDIM + er + tm * 16 + rr * 8], v);
        }
}

// ---------------- AV: single-product GEMM over eh, normalize at end ----------
// smem/stage: A(eh) 8KB @0, B(vth) 16KB @8192; 2 stages, stride 24576 (48KB).
__global__ __launch_bounds__(256) void av_mma()
{
    GEMM_PREAMBLE
    const int wm = wid & 1, wn = wid >> 1;
    const int h = blockIdx.y;
    const __half* Vh_ = g_vth + (size_t)(h >> 2) * DH * SDIM;

    const int ar = wm * 32 + (l & 7) + (l & 8);
    const int br = wn * 32 + (l & 7) + 8 * (l >> 4);

    for (int half = 0; half < 2; half++) {
        const int mt = half ? 31 - (int)blockIdx.x : (int)blockIdx.x;
        const int m0 = mt << 6;
        const int steps = mt + 1;
        const __half* Ae_ = g_eh + ((size_t)h * SDIM + m0) * SDIM;

        float acc[2][4][4];
#pragma unroll
        for (int i = 0; i < 2; i++)
#pragma unroll
            for (int j = 0; j < 4; j++)
#pragma unroll
                for (int r = 0; r < 4; r++) acc[i][j][r] = 0.f;

        LOAD64(sb, Ae_, SDIM, 0);
        LOAD128(sb + 8192u, Vh_, SDIM, 0);
        cp_commit();

        for (int s = 0; s < steps; s++) {
            cp_wait<0>();
            __syncthreads();
            if (s + 1 < steps) {
                uint32_t b2 = sb + ((s + 1) & 1) * 24576u;
                LOAD64(b2, Ae_, SDIM, s + 1);
                LOAD128(b2 + 8192u, Vh_, SDIM, s + 1);
                cp_commit();
            }
            const uint32_t Ast = sb + (s & 1) * 24576u;
            const uint32_t Bst = Ast + 8192u;
#pragma unroll
            for (int kk = 0; kk < 4; kk++) {
                uint32_t bf[4][2], af[2][4];
#pragma unroll
                for (int np = 0; np < 2; np++) {
                    uint32_t r0, r1, r2, r3;
                    ldm_x4(r0, r1, r2, r3,
                           Bst + (uint32_t)(br + np * 16) * 128u + 16u * (((kk << 1) + bkh) ^ lsw));
                    bf[2*np][0] = r0; bf[2*np][1] = r1; bf[2*np+1][0] = r2; bf[2*np+1][1] = r3;
                }
#pragma unroll
                for (int tm = 0; tm < 2; tm++)
                    ldm_x4(af[tm][0], af[tm][1], af[tm][2], af[tm][3],
                           Ast + (uint32_t)(ar + tm * 16) * 128u + 16u * (((kk << 1) + akh) ^ lsw));
#pragma unroll
                for (int tm = 0; tm < 2; tm++)
#pragma unroll
                    for (int tn = 0; tn < 4; tn++) mma_f16(acc[tm][tn], af[tm], bf[tn]);
            }
        }
        // epilogue: normalize by rowsum (scale cancels) and store fp16
        const int er = m0 + wm * 32 + (l >> 2);
        const int ecl = wn * 32 + 2 * (l & 3);
#pragma unroll
        for (int tm = 0; tm < 2; tm++) {
            float ir0 = 1.f / g_rs[h * SDIM + er + tm * 16];
            float ir1 = 1.f / g_rs[h * SDIM + er + tm * 16 + 8];
#pragma unroll
            for (int tn = 0; tn < 4; tn++) {
                int c = h * DH + ecl + tn * 8;
                int r0 = er + tm * 16, r1 = r0 + 8;
                __half h00 = __float2half_rn(acc[tm][tn][0] * ir0);
                __half h01 = __float2half_rn(acc[tm][tn][1] * ir0);
                __half h10 = __float2half_rn(acc[tm][tn][2] * ir1);
                __half h11 = __float2half_rn(acc[tm][tn][3] * ir1);
                ((uint32_t*)g_aoh)[(size_t)r0 * (EDIM/2) + (c >> 1)] =
                    (uint32_t)__half_as_ushort(h00) | ((uint32_t)__half_as_ushort(h01) << 16);
                ((uint32_t*)g_aoh)[(size_t)r1 * (EDIM/2) + (c >> 1)] =
                    (uint32_t)__half_as_ushort(h10) | ((uint32_t)__half_as_ushort(h11) << 16);
            }
        }
        __syncthreads();
    }
}

// ---------------- fused RMSNorm + RoPE + fill qa (qh + bias) ----------------
__global__ __launch_bounds__(128) void norm_fill_qa(
    const float* __restrict__ w, const float* __restrict__ gscale)
{
    const int s = blockIdx.x, h = blockIdx.y, d = threadIdx.x;
    float v = g_pr[(size_t)s * NOUT + CQ + h * DH + d];
    float ss = v * v;
#pragma unroll
    for (int o = 16; o; o >>= 1) ss += __shfl_xor_sync(0xffffffffu, ss, o);
    __shared__ float r4[4];
    __shared__ float sh[DH];
    if ((d & 31) == 0) r4[d >> 5] = ss;
    __syncthreads();
    float nv = v * rsqrtf((r4[0]+r4[1]+r4[2]+r4[3]) * (1.f / DH) + 1e-6f) * w[d];
    sh[d] = nv;
    __syncthreads();
    const int dm = d & 63;
    float f = 1.f / powf(10000.f, (float)(2 * dm) * (1.f / DH));
    float cs, sn; sincosf((float)s * f, &sn, &cs);
    float rot = (d < 64) ? -sh[d + 64] : sh[d - 64];
    float qs = (nv * cs + rot * sn) * 0.08838834764831845f;

    __half* row = g_qa + ((size_t)h * SDIM + s) * KQ;
    row[d] = __float2half_rn(qs);
    if (d < 32) {
        float bv = 0.f;
        if (h < NHG) bv = gscale[h] * (h < NSYM ? 0.5f : 1.f)
                         * g_pr[(size_t)s * NOUT + CRQ + h * RDIM + d];
        row[128 + d] = __float2half_rn(bv);
    } else if (d < 64) {
        int r = d - 32;
        float bv = 0.f;
        if (h < NSYM) bv = gscale[h] * 0.5f * g_pr[(size_t)s * NOUT + CRK + h * RDIM + r];
        row[160 + r] = __float2half_rn(bv);
    }
}

// ---------------- fused RMSNorm + RoPE + fill kb (kh + bias) ----------------
__global__ __launch_bounds__(128) void norm_fill_kb(const float* __restrict__ w)
{
    const int s = blockIdx.x, kvh = blockIdx.y, d = threadIdx.x;
    float v = g_pr[(size_t)s * NOUT + CK + kvh * DH + d];
    float ss = v * v;
#pragma unroll
    for (int o = 16; o; o >>= 1) ss += __shfl_xor_sync(0xffffffffu, ss, o);
    __shared__ float r4[4];
    __shared__ float sh[DH];
    if ((d & 31) == 0) r4[d >> 5] = ss;
    __syncthreads();
    float nv = v * rsqrtf((r4[0]+r4[1]+r4[2]+r4[3]) * (1.f / DH) + 1e-6f) * w[d];
    sh[d] = nv;
    __syncthreads();
    const int dm = d & 63;
    float f = 1.f / powf(10000.f, (float)(2 * dm) * (1.f / DH));
    float cs, sn; sincosf((float)s * f, &sn, &cs);
    float rot = (d < 64) ? -sh[d + 64] : sh[d - 64];
    __half kh = __float2half_rn(nv * cs + rot * sn);

#pragma unroll
    for (int e = 0; e < 4; e++) {
        int h = kvh * 4 + e;
        __half* row = g_kb + ((size_t)h * SDIM + s) * KQ;
        row[d] = kh;
        if (d < 32) {
            float bv = (h < NHG) ? g_pr[(size_t)s * NOUT + CRK + h * RDIM + d] : 0.f;
            row[128 + d] = __float2half_rn(bv);
        } else if (d < 64) {
            int r = d - 32;
            float bv = (h < NSYM) ? g_pr[(size_t)s * NOUT + CRQ + h * RDIM + r] : 0.f;
            row[160 + r] = __float2half_rn(bv);
        }
    }
}

// ---------------- fill vth (smem transpose, fp16 single) ----------------
__global__ __launch_bounds__(128) void fill_vh()
{
    __shared__ float sm[64][129];
    const int jb = blockIdx.x, kvh = blockIdx.y;
    const int tid = threadIdx.x;
    for (int jj = 0; jj < 64; jj++)
        sm[jj][tid] = g_pr[(size_t)(jb * 64 + jj) * NOUT + CV + kvh * DH + tid];
    __syncthreads();
    const int w = tid >> 5, ln = tid & 31;
    for (int d = w; d < DH; d += 4) {
        __half h0 = __float2half_rn(sm[2*ln][d]);
        __half h1 = __float2half_rn(sm[2*ln+1][d]);
        uint32_t* oh = (uint32_t*)(g_vth + (size_t)(kvh * DH + d) * SDIM + jb * 64);
        oh[ln] = (uint32_t)__half_as_ushort(h0) | ((uint32_t)__half_as_ushort(h1) << 16);
    }
}

// ---------------- Host ----------------
extern "C" void kernel_launch(void* const* d_in, const int* in_sizes, int n_in,
                              void* d_out, int out_size)
{
    const float* x   = (const float*)d_in[0];
    const float* Wq  = (const float*)d_in[1];
    const float* Wk  = (const float*)d_in[2];
    const float* Wv  = (const float*)d_in[3];
    const float* Wo  = (const float*)d_in[4];
    const float* qnw = (const float*)d_in[5];
    const float* knw = (const float*)d_in[6];
    const float* Wrq = (const float*)d_in[7];
    const float* Wrk = (const float*)d_in[8];
    const float* gsc = (const float*)d_in[9];
    float* out = (float*)d_out;

    float *pr, *rs;
    __half *xh, *wh, *woh, *aoh;
    cudaGetSymbolAddress((void**)&pr,  g_pr);
    cudaGetSymbolAddress((void**)&rs,  g_rs);
    cudaGetSymbolAddress((void**)&xh,  g_xh);
    cudaGetSymbolAddress((void**)&wh,  g_wh);
    cudaGetSymbolAddress((void**)&woh, g_woh);
    cudaGetSymbolAddress((void**)&aoh, g_aoh);

    cudaFuncSetAttribute(gemm1,      cudaFuncAttributeMaxDynamicSharedMemorySize, 49152);
    cudaFuncSetAttribute(scores_mma, cudaFuncAttributeMaxDynamicSharedMemorySize, 98304);
    cudaFuncSetAttribute(av_mma,     cudaFuncAttributeMaxDynamicSharedMemorySize, 49152);

    split_x<<<8192, 256>>>(x, xh, SDIM*EDIM/2);
    split_w1<<<12288, 256>>>(Wq, Wk, Wv);
    split_w2<<<11264, 256>>>(Wrq, Wrk, Wo);

    // index 3 under ncu: merged projection GEMM (single-product fp16)
    gemm1<<<dim3(NOUT/128, SDIM/64), 256, 49152>>>(xh, wh, pr, NOUT, EDIM);

    cudaMemsetAsync(rs, 0, NH * SDIM * sizeof(float));

    norm_fill_qa<<<dim3(SDIM, NH),  128>>>(qnw, gsc);
    norm_fill_kb<<<dim3(SDIM, NKV), 128>>>(knw);
    fill_vh<<<dim3(SDIM/64, NKV), 128>>>();

    scores_mma<<<dim3(136, NH), 256, 98304>>>();
    av_mma<<<dim3(16, NH), 256, 49152>>>();

    gemm1<<<dim3(EDIM/128, SDIM/64), 256, 49152>>>(aoh, woh, out, EDIM, EDIM);
}